// round 7
// baseline (speedup 1.0000x reference)
#include <cuda_runtime.h>
#include <cuda_bf16.h>
#include <math.h>
#include <stdint.h>

// ---------------- problem constants ----------------
#define Bq   16
#define LQn  512
#define LKVn 512
#define Dm   768
#define Hn   12
#define HDn  64
#define HIDn 3072
#define NTOK (Bq*LQn)          // 8192

// ---------------- scratch (device globals) ----------------
__device__ __align__(16) __nv_bfloat16 g_x_hi  [NTOK*Dm],  g_x_lo  [NTOK*Dm];
__device__ __align__(16) __nv_bfloat16 g_xkv_hi[NTOK*Dm],  g_xkv_lo[NTOK*Dm];
__device__ __align__(16) __nv_bfloat16 g_attn_hi[NTOK*Dm], g_attn_lo[NTOK*Dm];
__device__ __align__(16) __nv_bfloat16 g_hid_hi[NTOK*HIDn], g_hid_lo[NTOK*HIDn];
__device__ unsigned g_qkv [NTOK*3*Dm];
__device__ unsigned g_qh  [NTOK*Dm];
__device__ unsigned g_kvp [NTOK*2*Dm];
__device__ float    g_q1  [NTOK*Dm];
__device__ float    g_q2  [NTOK*Dm];
__device__ __align__(16) __nv_bfloat16 g_wqkv_hi [3*Dm*Dm], g_wqkv_lo [3*Dm*Dm];
__device__ __align__(16) __nv_bfloat16 g_wsa_hi  [Dm*Dm],   g_wsa_lo  [Dm*Dm];
__device__ __align__(16) __nv_bfloat16 g_wcaq_hi [Dm*Dm],   g_wcaq_lo [Dm*Dm];
__device__ __align__(16) __nv_bfloat16 g_wcakv_hi[2*Dm*Dm], g_wcakv_lo[2*Dm*Dm];
__device__ __align__(16) __nv_bfloat16 g_wcap_hi [Dm*Dm],   g_wcap_lo [Dm*Dm];
__device__ __align__(16) __nv_bfloat16 g_wfc1_hi [HIDn*Dm], g_wfc1_lo [HIDn*Dm];
__device__ __align__(16) __nv_bfloat16 g_wfc2_hi [Dm*HIDn], g_wfc2_lo [Dm*HIDn];

// ---------------- helpers ----------------
__device__ __forceinline__ unsigned pack_bf(float x){
    __nv_bfloat16 h = __float2bfloat16(x);
    float hf = __bfloat162float(h);
    __nv_bfloat16 l = __float2bfloat16(x - hf);
    return (unsigned)__bfloat16_as_ushort(h) | ((unsigned)__bfloat16_as_ushort(l) << 16);
}
__device__ __forceinline__ float warp_sum(float v){
#pragma unroll
    for (int o = 16; o > 0; o >>= 1) v += __shfl_xor_sync(0xffffffffu, v, o);
    return v;
}
__device__ __forceinline__ void mma16816(float* c, const unsigned* a, const unsigned* b){
    asm volatile(
        "mma.sync.aligned.m16n8k16.row.col.f32.bf16.bf16.f32 "
        "{%0,%1,%2,%3},{%4,%5,%6,%7},{%8,%9},{%0,%1,%2,%3};"
        : "+f"(c[0]), "+f"(c[1]), "+f"(c[2]), "+f"(c[3])
        : "r"(a[0]), "r"(a[1]), "r"(a[2]), "r"(a[3]), "r"(b[0]), "r"(b[1]));
}
__device__ __forceinline__ void cp16(void* smem_dst, const void* gsrc){
    unsigned s = (unsigned)__cvta_generic_to_shared(smem_dst);
    asm volatile("cp.async.cg.shared.global [%0], [%1], 16;\n" :: "r"(s), "l"(gsrc));
}
__device__ __forceinline__ void cp16a(uint32_t smem_addr, const void* gsrc){
    asm volatile("cp.async.cg.shared.global [%0], [%1], 16;\n" :: "r"(smem_addr), "l"(gsrc));
}
#define CP_COMMIT()  asm volatile("cp.async.commit_group;\n" ::: "memory")
#define CP_WAIT_2()  asm volatile("cp.async.wait_group 2;\n" ::: "memory")
#define CP_WAIT_1()  asm volatile("cp.async.wait_group 1;\n" ::: "memory")
#define CP_WAIT_0()  asm volatile("cp.async.wait_group 0;\n" ::: "memory")

__device__ __forceinline__ void ldsm4(unsigned& r0, unsigned& r1, unsigned& r2, unsigned& r3,
                                      uint32_t addr){
    asm volatile("ldmatrix.sync.aligned.m8n8.x4.shared.b16 {%0,%1,%2,%3}, [%4];"
        : "=r"(r0), "=r"(r1), "=r"(r2), "=r"(r3) : "r"(addr));
}

__device__ __forceinline__ void pack2(float p0, float p1, unsigned& hi, unsigned& lo){
    asm("cvt.rn.bf16x2.f32 %0, %1, %2;" : "=r"(hi) : "f"(p1), "f"(p0));
    float h0 = __uint_as_float(hi << 16);
    float h1 = __uint_as_float(hi & 0xffff0000u);
    asm("cvt.rn.bf16x2.f32 %0, %1, %2;" : "=r"(lo) : "f"(p1 - h1), "f"(p0 - h0));
}

// ---------------- weight conversion -> planes ----------------
struct CvtArgs {
    const float*   s[7];
    __nv_bfloat16* dh[7];
    __nv_bfloat16* dl[7];
    int            n[7];
};
__global__ void cvt_all(CvtArgs a){
    const int seg = blockIdx.y;
    const int i = blockIdx.x * 256 + threadIdx.x;
    if (i < a.n[seg]) {
        float x = a.s[seg][i];
        __nv_bfloat16 h = __float2bfloat16(x);
        a.dh[seg][i] = h;
        a.dl[seg][i] = __float2bfloat16(x - __bfloat162float(h));
    }
}

// ---------------- LayerNorm -> hi/lo planes ----------------
__global__ void ln_kernel(const float* __restrict__ x, const float* __restrict__ g,
                          const float* __restrict__ b,
                          __nv_bfloat16* __restrict__ yh, __nv_bfloat16* __restrict__ yl)
{
    __shared__ float sh[8];
    const long row = blockIdx.x;
    const float* xr = x + row * Dm;
    const int tid = threadIdx.x;
    const int w = tid >> 5, l = tid & 31;

    float v0 = xr[tid], v1 = xr[tid + 256], v2 = xr[tid + 512];

    float s = warp_sum(v0 + v1 + v2);
    if (l == 0) sh[w] = s;
    __syncthreads();
    if (w == 0) { float t = (l < 8) ? sh[l] : 0.f; t = warp_sum(t); if (l == 0) sh[0] = t; }
    __syncthreads();
    const float mean = sh[0] * (1.f / 768.f);
    __syncthreads();

    const float d0 = v0 - mean, d1 = v1 - mean, d2 = v2 - mean;
    float s2 = warp_sum(d0*d0 + d1*d1 + d2*d2);
    if (l == 0) sh[w] = s2;
    __syncthreads();
    if (w == 0) { float t = (l < 8) ? sh[l] : 0.f; t = warp_sum(t); if (l == 0) sh[0] = t; }
    __syncthreads();
    const float inv = rsqrtf(sh[0] * (1.f / 768.f) + 1e-5f);

#pragma unroll
    for (int t = 0; t < 3; t++) {
        const int i = tid + t * 256;
        const float d = (t == 0 ? d0 : (t == 1 ? d1 : d2));
        float v = d * inv * g[i] + b[i];
        __nv_bfloat16 h = __float2bfloat16(v);
        yh[row * Dm + i] = h;
        yl[row * Dm + i] = __float2bfloat16(v - __bfloat162float(h));
    }
}

// ---------------- fused flash attention (packed u32 in, planes out) ----------------
#define QS_ST 72
#define KS_ST 72
#define VS_ST 68
#define Q_TILE (128*QS_ST)
#define K_TILE (128*KS_ST)
#define V_TILE (128*VS_ST)
#define FLASH_SMEM ((Q_TILE + 2*K_TILE + 2*V_TILE) * 4)

__global__ void __launch_bounds__(256, 1)
flash_kernel(const unsigned* __restrict__ Q, int ldq, long Qb,
             const unsigned* __restrict__ K, int ldk, long Kb,
             const unsigned* __restrict__ V, int ldv, long Vb,
             __nv_bfloat16* __restrict__ Oh, __nv_bfloat16* __restrict__ Ol,
             int ldo, long Ob)
{
    extern __shared__ unsigned sm[];
    unsigned* Qs = sm;
    unsigned* Ks = sm + Q_TILE;
    unsigned* Vs = sm + Q_TILE + 2*K_TILE;

    const int tid  = threadIdx.x;
    const int wid  = tid >> 5, lane = tid & 31;
    const int g    = lane >> 2, t2 = (lane & 3) * 2;
    const int m0   = blockIdx.x * 128;
    const int wrow = wid * 16;

    {
        const int z = blockIdx.y;
        const int bb = z / Hn, hh = z - bb * Hn;
        Q += (long)bb * Qb + hh * 64;
        K += (long)bb * Kb + hh * 64;
        V += (long)bb * Vb + hh * 64;
        Oh += (long)bb * Ob + hh * 64;
        Ol += (long)bb * Ob + hh * 64;
    }

    auto loadQ = [&](){
#pragma unroll
        for (int idx = tid; idx < 2048; idx += 256) {
            const int r = idx >> 4, c = idx & 15;
            cp16(&Qs[r * QS_ST + c * 4], Q + (long)(m0 + r) * ldq + c * 4);
        }
    };
    auto loadK = [&](int kt, int s){
        unsigned* dst = Ks + s * K_TILE;
#pragma unroll
        for (int idx = tid; idx < 2048; idx += 256) {
            const int r = idx >> 4, c = idx & 15;
            cp16(&dst[r * KS_ST + c * 4], K + (long)(kt * 128 + r) * ldk + c * 4);
        }
    };
    auto loadV = [&](int kt, int s){
        unsigned* dst = Vs + s * V_TILE;
#pragma unroll
        for (int idx = tid; idx < 2048; idx += 256) {
            const int r = idx >> 4, c = idx & 15;
            cp16(&dst[r * VS_ST + c * 4], V + (long)(kt * 128 + r) * ldv + c * 4);
        }
    };

    float o[8][4];
#pragma unroll
    for (int i = 0; i < 8; i++)
#pragma unroll
        for (int j = 0; j < 4; j++) o[i][j] = 0.f;
    float m_a = -1e30f, m_b = -1e30f, l_a = 0.f, l_b = 0.f;

    loadQ(); loadK(0, 0); loadV(0, 0); CP_COMMIT();
    loadK(1, 1); loadV(1, 1); CP_COMMIT();

    for (int it = 0; it < 4; it++) {
        if (it >= 1) {
            __syncthreads();
            if (it + 1 < 4) { loadK(it + 1, (it + 1) & 1); loadV(it + 1, (it + 1) & 1); CP_COMMIT(); }
        }
        if (it + 1 < 4) CP_WAIT_1(); else CP_WAIT_0();
        __syncthreads();

        const unsigned* Kc = Ks + (it & 1) * K_TILE;
        const unsigned* Vc = Vs + (it & 1) * V_TILE;

        float s[16][4];
#pragma unroll
        for (int nt = 0; nt < 16; nt++)
#pragma unroll
            for (int c = 0; c < 4; c++) s[nt][c] = 0.f;

#pragma unroll
        for (int kk = 0; kk < 64; kk += 16) {
            const int r = wrow + g;
            uint2 a0 = *(const uint2*)&Qs[r       * QS_ST + kk + t2];
            uint2 a1 = *(const uint2*)&Qs[(r + 8) * QS_ST + kk + t2];
            uint2 a2 = *(const uint2*)&Qs[r       * QS_ST + kk + t2 + 8];
            uint2 a3 = *(const uint2*)&Qs[(r + 8) * QS_ST + kk + t2 + 8];
            unsigned rah[4], ral[4];
            rah[0] = __byte_perm(a0.x, a0.y, 0x5410); ral[0] = __byte_perm(a0.x, a0.y, 0x7632);
            rah[1] = __byte_perm(a1.x, a1.y, 0x5410); ral[1] = __byte_perm(a1.x, a1.y, 0x7632);
            rah[2] = __byte_perm(a2.x, a2.y, 0x5410); ral[2] = __byte_perm(a2.x, a2.y, 0x7632);
            rah[3] = __byte_perm(a3.x, a3.y, 0x5410); ral[3] = __byte_perm(a3.x, a3.y, 0x7632);
#pragma unroll
            for (int nt = 0; nt < 16; nt++) {
                const int kr = nt * 8 + g;
                uint2 v0 = *(const uint2*)&Kc[kr * KS_ST + kk + t2];
                uint2 v1 = *(const uint2*)&Kc[kr * KS_ST + kk + t2 + 8];
                unsigned bh[2], bl[2];
                bh[0] = __byte_perm(v0.x, v0.y, 0x5410); bl[0] = __byte_perm(v0.x, v0.y, 0x7632);
                bh[1] = __byte_perm(v1.x, v1.y, 0x5410); bl[1] = __byte_perm(v1.x, v1.y, 0x7632);
                mma16816(s[nt], rah, bh);
                mma16816(s[nt], ral, bh);
                mma16816(s[nt], rah, bl);
            }
        }

        float mx_a = -1e30f, mx_b = -1e30f;
#pragma unroll
        for (int nt = 0; nt < 16; nt++) {
#pragma unroll
            for (int c = 0; c < 4; c++) s[nt][c] *= 0.125f;
            mx_a = fmaxf(mx_a, fmaxf(s[nt][0], s[nt][1]));
            mx_b = fmaxf(mx_b, fmaxf(s[nt][2], s[nt][3]));
        }
        mx_a = fmaxf(mx_a, __shfl_xor_sync(0xffffffffu, mx_a, 1));
        mx_a = fmaxf(mx_a, __shfl_xor_sync(0xffffffffu, mx_a, 2));
        mx_b = fmaxf(mx_b, __shfl_xor_sync(0xffffffffu, mx_b, 1));
        mx_b = fmaxf(mx_b, __shfl_xor_sync(0xffffffffu, mx_b, 2));

        const float nm_a = fmaxf(m_a, mx_a);
        const float nm_b = fmaxf(m_b, mx_b);
        const float sc_a = __expf(m_a - nm_a);
        const float sc_b = __expf(m_b - nm_b);
        m_a = nm_a; m_b = nm_b;
        l_a *= sc_a; l_b *= sc_b;
#pragma unroll
        for (int nt = 0; nt < 8; nt++) {
            o[nt][0] *= sc_a; o[nt][1] *= sc_a;
            o[nt][2] *= sc_b; o[nt][3] *= sc_b;
        }
        float sum_a = 0.f, sum_b = 0.f;
#pragma unroll
        for (int nt = 0; nt < 16; nt++) {
            s[nt][0] = __expf(s[nt][0] - nm_a);
            s[nt][1] = __expf(s[nt][1] - nm_a);
            s[nt][2] = __expf(s[nt][2] - nm_b);
            s[nt][3] = __expf(s[nt][3] - nm_b);
            sum_a += s[nt][0] + s[nt][1];
            sum_b += s[nt][2] + s[nt][3];
        }
        l_a += sum_a; l_b += sum_b;

#pragma unroll
        for (int ks = 0; ks < 8; ks++) {
            unsigned rah[4], ral[4];
            pack2(s[2*ks  ][0], s[2*ks  ][1], rah[0], ral[0]);
            pack2(s[2*ks  ][2], s[2*ks  ][3], rah[1], ral[1]);
            pack2(s[2*ks+1][0], s[2*ks+1][1], rah[2], ral[2]);
            pack2(s[2*ks+1][2], s[2*ks+1][3], rah[3], ral[3]);
#pragma unroll
            for (int nt = 0; nt < 8; nt++) {
                const int n = nt * 8 + g;
                unsigned w0 = Vc[(ks*16 + t2    ) * VS_ST + n];
                unsigned w1 = Vc[(ks*16 + t2 + 1) * VS_ST + n];
                unsigned w2 = Vc[(ks*16 + t2 + 8) * VS_ST + n];
                unsigned w3 = Vc[(ks*16 + t2 + 9) * VS_ST + n];
                unsigned bh[2], bl[2];
                bh[0] = __byte_perm(w0, w1, 0x5410); bl[0] = __byte_perm(w0, w1, 0x7632);
                bh[1] = __byte_perm(w2, w3, 0x5410); bl[1] = __byte_perm(w2, w3, 0x7632);
                mma16816(o[nt], rah, bh);
                mma16816(o[nt], ral, bh);
                mma16816(o[nt], rah, bl);
            }
        }
    }

    l_a += __shfl_xor_sync(0xffffffffu, l_a, 1);
    l_a += __shfl_xor_sync(0xffffffffu, l_a, 2);
    l_b += __shfl_xor_sync(0xffffffffu, l_b, 1);
    l_b += __shfl_xor_sync(0xffffffffu, l_b, 2);
    const float inv_a = 1.f / l_a;
    const float inv_b = 1.f / l_b;

    const int row_a = m0 + wrow + g;
    const int row_b = row_a + 8;
#pragma unroll
    for (int nt = 0; nt < 8; nt++) {
        const int col = nt * 8 + t2;
        unsigned p0 = pack_bf(o[nt][0] * inv_a), p1 = pack_bf(o[nt][1] * inv_a);
        unsigned p2 = pack_bf(o[nt][2] * inv_b), p3 = pack_bf(o[nt][3] * inv_b);
        *(unsigned*)&Oh[(long)row_a * ldo + col] = __byte_perm(p0, p1, 0x5410);
        *(unsigned*)&Ol[(long)row_a * ldo + col] = __byte_perm(p0, p1, 0x7632);
        *(unsigned*)&Oh[(long)row_b * ldo + col] = __byte_perm(p2, p3, 0x5410);
        *(unsigned*)&Ol[(long)row_b * ldo + col] = __byte_perm(p2, p3, 0x7632);
    }
}

// ---------------- bf16-split GEMM: BM=128, BN=256, BK=32, 3-stage, 8 warps 64x64 ----------------
// OUTMODE: 0 = fp32 (+bias/resid), 1 = packed u32, 2 = planes. ACT==1: exact GELU.
#define PL_ST 40                     // bf16 row stride (80 B): conflict-free LDSM phases
#define PL_ST2 (PL_ST*2)             // bytes per row
#define A_PLANE (128*PL_ST2)         // 10240 B
#define B_PLANE (256*PL_ST2)         // 20480 B
#define PL_STAGE (2*A_PLANE + 2*B_PLANE)  // 61440 B: [Ahi|Alo|Bhi|Blo]
#define PL_SMEM  (3*PL_STAGE)        // 184320 B

template<int OUTMODE, int ACT>
__global__ void __launch_bounds__(256, 1)
pl_gemm(const __nv_bfloat16* __restrict__ Ahi, const __nv_bfloat16* __restrict__ Alo, int lda,
        const __nv_bfloat16* __restrict__ Bhi, const __nv_bfloat16* __restrict__ Blo, int ldb,
        void* __restrict__ Cp, void* __restrict__ Cs, int ldc,
        int K,
        const float* __restrict__ bias,
        const float* __restrict__ resid, int ldr)
{
    extern __shared__ char smc[];
    const uint32_t smb = (uint32_t)__cvta_generic_to_shared(smc);

    const int tid = threadIdx.x;
    const int wid = tid >> 5, lane = tid & 31;
    const int wm = wid >> 2, wn = wid & 3;           // 2 x 4 grid of 64 x 64 warp tiles
    const int g  = lane >> 2, t2 = (lane & 3) * 2;
    const int l8 = lane & 7, q = lane >> 3;

    const int m0 = blockIdx.y * 128, n0 = blockIdx.x * 256;

    // ldmatrix per-thread base addresses (within stage 0, hi planes)
    const int rowA = (q & 1) * 8 + l8, colA = (q >> 1) * 8;
    const int rowB = (q >> 1) * 8 + l8, colB = (q & 1) * 8;
    const uint32_t aA = smb + ((wm*64 + rowA) * PL_ST + colA) * 2;
    const uint32_t aB = smb + 2*A_PLANE + ((wn*64 + rowB) * PL_ST + colB) * 2;

    float acc[4][8][4];
#pragma unroll
    for (int i = 0; i < 4; i++)
#pragma unroll
        for (int j = 0; j < 8; j++)
#pragma unroll
            for (int c = 0; c < 4; c++) acc[i][j][c] = 0.f;

    auto load_plane_128 = [&](const __nv_bfloat16* src, int ld, uint32_t dstoff){
#pragma unroll
        for (int idx = tid; idx < 512; idx += 256) {
            const int r = idx >> 2, c = idx & 3;
            cp16a(smb + dstoff + r * PL_ST2 + c * 16, src + (long)r * ld + c * 8);
        }
    };
    auto load_plane_256 = [&](const __nv_bfloat16* src, int ld, uint32_t dstoff){
#pragma unroll
        for (int idx = tid; idx < 1024; idx += 256) {
            const int r = idx >> 2, c = idx & 3;
            cp16a(smb + dstoff + r * PL_ST2 + c * 16, src + (long)r * ld + c * 8);
        }
    };
    auto load_chunk = [&](int k0, int s){
        const uint32_t so = s * PL_STAGE;
        load_plane_128(Ahi + (long)m0 * lda + k0, lda, so);
        load_plane_128(Alo + (long)m0 * lda + k0, lda, so + A_PLANE);
        load_plane_256(Bhi + (long)n0 * ldb + k0, ldb, so + 2*A_PLANE);
        load_plane_256(Blo + (long)n0 * ldb + k0, ldb, so + 2*A_PLANE + B_PLANE);
    };

    const int iters = K / 32;                        // >= 24 for all our shapes
    load_chunk(0, 0);  CP_COMMIT();
    load_chunk(32, 1); CP_COMMIT();
    load_chunk(64, 2); CP_COMMIT();

    int stage = 0;
    for (int it = 0; it < iters; it++) {
        if (it <= iters - 3)      CP_WAIT_2();
        else if (it == iters - 2) CP_WAIT_1();
        else                      CP_WAIT_0();
        __syncthreads();

        const uint32_t so = stage * PL_STAGE;

#pragma unroll
        for (int kk = 0; kk < 32; kk += 16) {
            const uint32_t ko = kk * 2;
            // B fragments for 8 n-tiles, both planes: 8 ldsm.x4
            unsigned bh[8][2], bl[8][2];
#pragma unroll
            for (int p = 0; p < 4; p++) {
                ldsm4(bh[2*p][0], bh[2*p][1], bh[2*p+1][0], bh[2*p+1][1],
                      aB + so + ko + p * 16 * PL_ST2);
                ldsm4(bl[2*p][0], bl[2*p][1], bl[2*p+1][0], bl[2*p+1][1],
                      aB + so + ko + p * 16 * PL_ST2 + B_PLANE);
            }
#pragma unroll
            for (int mt = 0; mt < 4; mt++) {
                const uint32_t amo = so + ko + mt * 16 * PL_ST2;
                unsigned ah[4], al[4];
                ldsm4(ah[0], ah[1], ah[2], ah[3], aA + amo);
                ldsm4(al[0], al[1], al[2], al[3], aA + amo + A_PLANE);
#pragma unroll
                for (int nt = 0; nt < 8; nt++) {
                    mma16816(acc[mt][nt], ah, bh[nt]);
                    mma16816(acc[mt][nt], al, bh[nt]);
                    mma16816(acc[mt][nt], ah, bl[nt]);
                }
            }
        }
        __syncthreads();
        if (it + 3 < iters) { load_chunk((it + 3) * 32, stage); CP_COMMIT(); }
        stage = (stage == 2) ? 0 : stage + 1;
    }

    // ---------------- epilogue ----------------
#pragma unroll
    for (int mt = 0; mt < 4; mt++) {
#pragma unroll
        for (int nt = 0; nt < 8; nt++) {
            const int row0 = m0 + wm * 64 + mt * 16 + g;
            const int col  = n0 + wn * 64 + nt * 8 + t2;
#pragma unroll
            for (int half = 0; half < 2; half++) {
                const int row = row0 + half * 8;
                float v0 = acc[mt][nt][half * 2 + 0];
                float v1 = acc[mt][nt][half * 2 + 1];
                if (bias)  { v0 += bias[col]; v1 += bias[col + 1]; }
                if (resid) { v0 += resid[(long)row * ldr + col];
                             v1 += resid[(long)row * ldr + col + 1]; }
                if (ACT == 1) {
                    v0 = 0.5f * v0 * (1.0f + erff(v0 * 0.70710678118654752f));
                    v1 = 0.5f * v1 * (1.0f + erff(v1 * 0.70710678118654752f));
                }
                if (OUTMODE == 0) {
                    float2 w; w.x = v0; w.y = v1;
                    *(float2*)((float*)Cp + (long)row * ldc + col) = w;
                } else if (OUTMODE == 1) {
                    uint2 w; w.x = pack_bf(v0); w.y = pack_bf(v1);
                    *(uint2*)((unsigned*)Cp + (long)row * ldc + col) = w;
                } else {
                    unsigned p0 = pack_bf(v0), p1 = pack_bf(v1);
                    *(unsigned*)((__nv_bfloat16*)Cp + (long)row * ldc + col) = __byte_perm(p0, p1, 0x5410);
                    *(unsigned*)((__nv_bfloat16*)Cs + (long)row * ldc + col) = __byte_perm(p0, p1, 0x7632);
                }
            }
        }
    }
}

// ---------------- launcher ----------------
extern "C" void kernel_launch(void* const* d_in, const int* in_sizes, int n_in,
                              void* d_out, int out_size)
{
    const float* q     = (const float*)d_in[0];
    const float* kv    = (const float*)d_in[1];
    const float* n1g   = (const float*)d_in[2];
    const float* n1b   = (const float*)d_in[3];
    const float* qkv_w = (const float*)d_in[4];
    const float* sa_pw = (const float*)d_in[5];
    const float* sa_pb = (const float*)d_in[6];
    const float* n2qg  = (const float*)d_in[7];
    const float* n2qb  = (const float*)d_in[8];
    const float* n2kg  = (const float*)d_in[9];
    const float* n2kb  = (const float*)d_in[10];
    const float* caq_w = (const float*)d_in[11];
    const float* cakv_w= (const float*)d_in[12];
    const float* cap_w = (const float*)d_in[13];
    const float* cap_b = (const float*)d_in[14];
    const float* n3g   = (const float*)d_in[15];
    const float* n3b   = (const float*)d_in[16];
    const float* fc1w  = (const float*)d_in[17];
    const float* fc1b  = (const float*)d_in[18];
    const float* fc2w  = (const float*)d_in[19];
    const float* fc2b  = (const float*)d_in[20];
    float* out = (float*)d_out;

    __nv_bfloat16 *xh,*xl,*xkh,*xkl,*ath,*atl,*hih,*hil;
    __nv_bfloat16 *wqh,*wql,*wsh,*wsl,*wqh2,*wql2,*wkh,*wkl,*wph,*wpl,*w1h,*w1l,*w2h,*w2l;
    unsigned *qkvb,*qh,*kvp;
    float *q1,*q2;
    cudaGetSymbolAddress((void**)&xh,  g_x_hi);   cudaGetSymbolAddress((void**)&xl,  g_x_lo);
    cudaGetSymbolAddress((void**)&xkh, g_xkv_hi); cudaGetSymbolAddress((void**)&xkl, g_xkv_lo);
    cudaGetSymbolAddress((void**)&ath, g_attn_hi);cudaGetSymbolAddress((void**)&atl, g_attn_lo);
    cudaGetSymbolAddress((void**)&hih, g_hid_hi); cudaGetSymbolAddress((void**)&hil, g_hid_lo);
    cudaGetSymbolAddress((void**)&qkvb,g_qkv);
    cudaGetSymbolAddress((void**)&qh,  g_qh);
    cudaGetSymbolAddress((void**)&kvp, g_kvp);
    cudaGetSymbolAddress((void**)&q1,  g_q1);
    cudaGetSymbolAddress((void**)&q2,  g_q2);
    cudaGetSymbolAddress((void**)&wqh, g_wqkv_hi); cudaGetSymbolAddress((void**)&wql, g_wqkv_lo);
    cudaGetSymbolAddress((void**)&wsh, g_wsa_hi);  cudaGetSymbolAddress((void**)&wsl, g_wsa_lo);
    cudaGetSymbolAddress((void**)&wqh2,g_wcaq_hi); cudaGetSymbolAddress((void**)&wql2,g_wcaq_lo);
    cudaGetSymbolAddress((void**)&wkh, g_wcakv_hi);cudaGetSymbolAddress((void**)&wkl, g_wcakv_lo);
    cudaGetSymbolAddress((void**)&wph, g_wcap_hi); cudaGetSymbolAddress((void**)&wpl, g_wcap_lo);
    cudaGetSymbolAddress((void**)&w1h, g_wfc1_hi); cudaGetSymbolAddress((void**)&w1l, g_wfc1_lo);
    cudaGetSymbolAddress((void**)&w2h, g_wfc2_hi); cudaGetSymbolAddress((void**)&w2l, g_wfc2_lo);

    cudaFuncSetAttribute(pl_gemm<0,0>, cudaFuncAttributeMaxDynamicSharedMemorySize, PL_SMEM);
    cudaFuncSetAttribute(pl_gemm<1,0>, cudaFuncAttributeMaxDynamicSharedMemorySize, PL_SMEM);
    cudaFuncSetAttribute(pl_gemm<2,1>, cudaFuncAttributeMaxDynamicSharedMemorySize, PL_SMEM);
    cudaFuncSetAttribute(flash_kernel, cudaFuncAttributeMaxDynamicSharedMemorySize, FLASH_SMEM);

    const dim3 blk(256);
    const long QKV_B = (long)LQn * 3 * Dm;
    const long TOK_B = (long)LQn * Dm;
    const long KVP_B = (long)LKVn * 2 * Dm;

    // ---- weight conversion ----
    {
        CvtArgs a;
        a.s[0]=qkv_w;  a.dh[0]=wqh;  a.dl[0]=wql;  a.n[0]=3*Dm*Dm;
        a.s[1]=sa_pw;  a.dh[1]=wsh;  a.dl[1]=wsl;  a.n[1]=Dm*Dm;
        a.s[2]=caq_w;  a.dh[2]=wqh2; a.dl[2]=wql2; a.n[2]=Dm*Dm;
        a.s[3]=cakv_w; a.dh[3]=wkh;  a.dl[3]=wkl;  a.n[3]=2*Dm*Dm;
        a.s[4]=cap_w;  a.dh[4]=wph;  a.dl[4]=wpl;  a.n[4]=Dm*Dm;
        a.s[5]=fc1w;   a.dh[5]=w1h;  a.dl[5]=w1l;  a.n[5]=HIDn*Dm;
        a.s[6]=fc2w;   a.dh[6]=w2h;  a.dl[6]=w2l;  a.n[6]=Dm*HIDn;
        cvt_all<<<dim3((HIDn*Dm + 255)/256, 7), 256>>>(a);
    }

    // ===== self-attention =====
    ln_kernel<<<NTOK, 256>>>(q, n1g, n1b, xh, xl);

    pl_gemm<1,0><<<dim3(3*Dm/256, NTOK/128), blk, PL_SMEM>>>(
        xh, xl, Dm, wqh, wql, Dm, qkvb, nullptr, 3*Dm, Dm, nullptr, nullptr, 0);

    flash_kernel<<<dim3(LQn/128, Bq*Hn), blk, FLASH_SMEM>>>(
        qkvb,        3*Dm, QKV_B,
        qkvb + Dm,   3*Dm, QKV_B,
        qkvb + 2*Dm, 3*Dm, QKV_B,
        ath, atl, Dm, TOK_B);

    pl_gemm<0,0><<<dim3(Dm/256, NTOK/128), blk, PL_SMEM>>>(
        ath, atl, Dm, wsh, wsl, Dm, q1, nullptr, Dm, Dm, sa_pb, q, Dm);

    // ===== cross-attention =====
    ln_kernel<<<NTOK, 256>>>(q1, n2qg, n2qb, xh, xl);
    ln_kernel<<<NTOK, 256>>>(kv, n2kg, n2kb, xkh, xkl);

    pl_gemm<1,0><<<dim3(Dm/256, NTOK/128), blk, PL_SMEM>>>(
        xh, xl, Dm, wqh2, wql2, Dm, qh, nullptr, Dm, Dm, nullptr, nullptr, 0);

    pl_gemm<1,0><<<dim3(2*Dm/256, NTOK/128), blk, PL_SMEM>>>(
        xkh, xkl, Dm, wkh, wkl, Dm, kvp, nullptr, 2*Dm, Dm, nullptr, nullptr, 0);

    flash_kernel<<<dim3(LQn/128, Bq*Hn), blk, FLASH_SMEM>>>(
        qh,        Dm,   TOK_B,
        kvp,       2*Dm, KVP_B,
        kvp + Dm,  2*Dm, KVP_B,
        ath, atl, Dm, TOK_B);

    pl_gemm<0,0><<<dim3(Dm/256, NTOK/128), blk, PL_SMEM>>>(
        ath, atl, Dm, wph, wpl, Dm, q2, nullptr, Dm, Dm, cap_b, q1, Dm);

    // ===== MLP =====
    ln_kernel<<<NTOK, 256>>>(q2, n3g, n3b, xh, xl);

    pl_gemm<2,1><<<dim3(HIDn/256, NTOK/128), blk, PL_SMEM>>>(
        xh, xl, Dm, w1h, w1l, Dm, hih, hil, HIDn, Dm, fc1b, nullptr, 0);

    pl_gemm<0,0><<<dim3(Dm/256, NTOK/128), blk, PL_SMEM>>>(
        hih, hil, HIDn, w2h, w2l, HIDn, out, nullptr, Dm, HIDn, fc2b, q2, Dm);
}

// round 8
// speedup vs baseline: 1.4817x; 1.4817x over previous
#include <cuda_runtime.h>
#include <cuda_fp16.h>
#include <math.h>

// ---------------- problem constants ----------------
#define Bq   16
#define LQn  512
#define LKVn 512
#define Dm   768
#define Hn   12
#define HDn  64
#define HIDn 3072
#define NTOK (Bq*LQn)          // 8192

// ---------------- scratch (device globals) ----------------
// packed fp16 hi/lo pairs stored as u32 (low16 = hi, high16 = lo)
__device__ unsigned g_x   [NTOK*Dm];
__device__ unsigned g_xkv [NTOK*Dm];
__device__ unsigned g_qkv [NTOK*3*Dm];
__device__ unsigned g_attn[NTOK*Dm];
__device__ unsigned g_qh  [NTOK*Dm];
__device__ unsigned g_kvp [NTOK*2*Dm];
__device__ float    g_q1  [NTOK*Dm];
__device__ float    g_q2  [NTOK*Dm];
__device__ unsigned g_hid [NTOK*HIDn];
// converted weights
__device__ unsigned g_wqkv [3*Dm*Dm];
__device__ unsigned g_wsa  [Dm*Dm];
__device__ unsigned g_wcaq [Dm*Dm];
__device__ unsigned g_wcakv[2*Dm*Dm];
__device__ unsigned g_wcap [Dm*Dm];
__device__ unsigned g_wfc1 [HIDn*Dm];
__device__ unsigned g_wfc2 [Dm*HIDn];

// ---------------- helpers ----------------
__device__ __forceinline__ unsigned pack_hl(float x){
    __half h = __float2half_rn(x);
    float hf = __half2float(h);
    __half l = __float2half_rn(x - hf);
    return (unsigned)__half_as_ushort(h) | ((unsigned)__half_as_ushort(l) << 16);
}

__device__ __forceinline__ float warp_sum(float v){
#pragma unroll
    for (int o = 16; o > 0; o >>= 1) v += __shfl_xor_sync(0xffffffffu, v, o);
    return v;
}

__device__ __forceinline__ void mma16816(float* c, const unsigned* a, const unsigned* b){
    asm volatile(
        "mma.sync.aligned.m16n8k16.row.col.f32.f16.f16.f32 "
        "{%0,%1,%2,%3},{%4,%5,%6,%7},{%8,%9},{%0,%1,%2,%3};"
        : "+f"(c[0]), "+f"(c[1]), "+f"(c[2]), "+f"(c[3])
        : "r"(a[0]), "r"(a[1]), "r"(a[2]), "r"(a[3]), "r"(b[0]), "r"(b[1]));
}

__device__ __forceinline__ void cp16(unsigned* smem_dst, const unsigned* gsrc){
    unsigned s = (unsigned)__cvta_generic_to_shared(smem_dst);
    asm volatile("cp.async.cg.shared.global [%0], [%1], 16;\n" :: "r"(s), "l"(gsrc));
}
#define CP_COMMIT()  asm volatile("cp.async.commit_group;\n" ::: "memory")
#define CP_WAIT_1()  asm volatile("cp.async.wait_group 1;\n" ::: "memory")
#define CP_WAIT_0()  asm volatile("cp.async.wait_group 0;\n" ::: "memory")

// split (p0,p1) into (hi,lo) f16x2 A-fragment registers: reg low16 = elem k, high16 = elem k+1
__device__ __forceinline__ void pack2(float p0, float p1, unsigned& hi, unsigned& lo){
    __half h0 = __float2half_rn(p0), h1 = __float2half_rn(p1);
    hi = (unsigned)__half_as_ushort(h0) | ((unsigned)__half_as_ushort(h1) << 16);
    __half l0 = __float2half_rn(p0 - __half2float(h0));
    __half l1 = __float2half_rn(p1 - __half2float(h1));
    lo = (unsigned)__half_as_ushort(l0) | ((unsigned)__half_as_ushort(l1) << 16);
}

// ---------------- merged weight conversion (blockIdx.y = segment) ----------------
struct CvtArgs {
    const float* s[7];
    unsigned*    d[7];
    int          n[7];
};
__global__ void cvt_all(CvtArgs a){
    const int seg = blockIdx.y;
    const int i = blockIdx.x * 256 + threadIdx.x;
    if (i < a.n[seg]) a.d[seg][i] = pack_hl(a.s[seg][i]);
}

// ---------------- LayerNorm -> packed fp16 hi/lo ----------------
__global__ void ln_kernel(const float* __restrict__ x, const float* __restrict__ g,
                          const float* __restrict__ b, unsigned* __restrict__ y)
{
    __shared__ float sh[8];
    const long row = blockIdx.x;
    const float* xr = x + row * Dm;
    unsigned* yr = y + row * Dm;
    const int tid = threadIdx.x;
    const int w = tid >> 5, l = tid & 31;

    float v0 = xr[tid], v1 = xr[tid + 256], v2 = xr[tid + 512];

    float s = warp_sum(v0 + v1 + v2);
    if (l == 0) sh[w] = s;
    __syncthreads();
    if (w == 0) { float t = (l < 8) ? sh[l] : 0.f; t = warp_sum(t); if (l == 0) sh[0] = t; }
    __syncthreads();
    const float mean = sh[0] * (1.f / 768.f);
    __syncthreads();

    const float d0 = v0 - mean, d1 = v1 - mean, d2 = v2 - mean;
    float s2 = warp_sum(d0*d0 + d1*d1 + d2*d2);
    if (l == 0) sh[w] = s2;
    __syncthreads();
    if (w == 0) { float t = (l < 8) ? sh[l] : 0.f; t = warp_sum(t); if (l == 0) sh[0] = t; }
    __syncthreads();
    const float inv = rsqrtf(sh[0] * (1.f / 768.f) + 1e-5f);

    yr[tid]       = pack_hl(d0 * inv * g[tid]       + b[tid]);
    yr[tid + 256] = pack_hl(d1 * inv * g[tid + 256] + b[tid + 256]);
    yr[tid + 512] = pack_hl(d2 * inv * g[tid + 512] + b[tid + 512]);
}

// ---------------- fused flash attention (128 Q-rows x 512 keys, hd=64) ----------------
#define QS_ST 72
#define KS_ST 72
#define VS_ST 68
#define Q_TILE (128*QS_ST)
#define K_TILE (128*KS_ST)
#define V_TILE (128*VS_ST)
#define FLASH_SMEM ((Q_TILE + 2*K_TILE + 2*V_TILE) * 4)

__global__ void __launch_bounds__(256, 1)
flash_kernel(const unsigned* __restrict__ Q, int ldq, long Qb,
             const unsigned* __restrict__ K, int ldk, long Kb,
             const unsigned* __restrict__ V, int ldv, long Vb,
             unsigned* __restrict__ O, int ldo, long Ob)
{
    extern __shared__ unsigned sm[];
    unsigned* Qs = sm;
    unsigned* Ks = sm + Q_TILE;
    unsigned* Vs = sm + Q_TILE + 2*K_TILE;

    const int tid  = threadIdx.x;
    const int wid  = tid >> 5, lane = tid & 31;
    const int g    = lane >> 2, t2 = (lane & 3) * 2;
    const int m0   = blockIdx.x * 128;
    const int wrow = wid * 16;

    {
        const int z = blockIdx.y;
        const int bb = z / Hn, hh = z - bb * Hn;
        Q += (long)bb * Qb + hh * 64;
        K += (long)bb * Kb + hh * 64;
        V += (long)bb * Vb + hh * 64;
        O += (long)bb * Ob + hh * 64;
    }

    auto loadQ = [&](){
#pragma unroll
        for (int idx = tid; idx < 2048; idx += 256) {
            const int r = idx >> 4, c = idx & 15;
            cp16(&Qs[r * QS_ST + c * 4], Q + (long)(m0 + r) * ldq + c * 4);
        }
    };
    auto loadK = [&](int kt, int s){
        unsigned* dst = Ks + s * K_TILE;
#pragma unroll
        for (int idx = tid; idx < 2048; idx += 256) {
            const int r = idx >> 4, c = idx & 15;
            cp16(&dst[r * KS_ST + c * 4], K + (long)(kt * 128 + r) * ldk + c * 4);
        }
    };
    auto loadV = [&](int kt, int s){
        unsigned* dst = Vs + s * V_TILE;
#pragma unroll
        for (int idx = tid; idx < 2048; idx += 256) {
            const int r = idx >> 4, c = idx & 15;
            cp16(&dst[r * VS_ST + c * 4], V + (long)(kt * 128 + r) * ldv + c * 4);
        }
    };

    float o[8][4];
#pragma unroll
    for (int i = 0; i < 8; i++)
#pragma unroll
        for (int j = 0; j < 4; j++) o[i][j] = 0.f;
    float m_a = -1e30f, m_b = -1e30f, l_a = 0.f, l_b = 0.f;

    loadQ(); loadK(0, 0); loadV(0, 0); CP_COMMIT();
    loadK(1, 1); loadV(1, 1); CP_COMMIT();

    for (int it = 0; it < 4; it++) {
        if (it >= 1) {
            __syncthreads();
            if (it + 1 < 4) { loadK(it + 1, (it + 1) & 1); loadV(it + 1, (it + 1) & 1); CP_COMMIT(); }
        }
        if (it + 1 < 4) CP_WAIT_1(); else CP_WAIT_0();
        __syncthreads();

        const unsigned* Kc = Ks + (it & 1) * K_TILE;
        const unsigned* Vc = Vs + (it & 1) * V_TILE;

        // ---- S = Q K^T : 2-term split (drop K-lo) ----
        float s[16][4];
#pragma unroll
        for (int nt = 0; nt < 16; nt++)
#pragma unroll
            for (int c = 0; c < 4; c++) s[nt][c] = 0.f;

#pragma unroll
        for (int kk = 0; kk < 64; kk += 16) {
            const int r = wrow + g;
            uint2 a0 = *(const uint2*)&Qs[r       * QS_ST + kk + t2];
            uint2 a1 = *(const uint2*)&Qs[(r + 8) * QS_ST + kk + t2];
            uint2 a2 = *(const uint2*)&Qs[r       * QS_ST + kk + t2 + 8];
            uint2 a3 = *(const uint2*)&Qs[(r + 8) * QS_ST + kk + t2 + 8];
            unsigned rah[4], ral[4];
            rah[0] = __byte_perm(a0.x, a0.y, 0x5410); ral[0] = __byte_perm(a0.x, a0.y, 0x7632);
            rah[1] = __byte_perm(a1.x, a1.y, 0x5410); ral[1] = __byte_perm(a1.x, a1.y, 0x7632);
            rah[2] = __byte_perm(a2.x, a2.y, 0x5410); ral[2] = __byte_perm(a2.x, a2.y, 0x7632);
            rah[3] = __byte_perm(a3.x, a3.y, 0x5410); ral[3] = __byte_perm(a3.x, a3.y, 0x7632);
#pragma unroll
            for (int nt = 0; nt < 16; nt++) {
                const int kr = nt * 8 + g;
                uint2 v0 = *(const uint2*)&Kc[kr * KS_ST + kk + t2];
                uint2 v1 = *(const uint2*)&Kc[kr * KS_ST + kk + t2 + 8];
                unsigned bh[2];
                bh[0] = __byte_perm(v0.x, v0.y, 0x5410);
                bh[1] = __byte_perm(v1.x, v1.y, 0x5410);
                mma16816(s[nt], rah, bh);
                mma16816(s[nt], ral, bh);
            }
        }

        // ---- online softmax (scale 1/8 folded) ----
        float mx_a = -1e30f, mx_b = -1e30f;
#pragma unroll
        for (int nt = 0; nt < 16; nt++) {
#pragma unroll
            for (int c = 0; c < 4; c++) s[nt][c] *= 0.125f;
            mx_a = fmaxf(mx_a, fmaxf(s[nt][0], s[nt][1]));
            mx_b = fmaxf(mx_b, fmaxf(s[nt][2], s[nt][3]));
        }
        mx_a = fmaxf(mx_a, __shfl_xor_sync(0xffffffffu, mx_a, 1));
        mx_a = fmaxf(mx_a, __shfl_xor_sync(0xffffffffu, mx_a, 2));
        mx_b = fmaxf(mx_b, __shfl_xor_sync(0xffffffffu, mx_b, 1));
        mx_b = fmaxf(mx_b, __shfl_xor_sync(0xffffffffu, mx_b, 2));

        const float nm_a = fmaxf(m_a, mx_a);
        const float nm_b = fmaxf(m_b, mx_b);
        const float sc_a = __expf(m_a - nm_a);
        const float sc_b = __expf(m_b - nm_b);
        m_a = nm_a; m_b = nm_b;
        l_a *= sc_a; l_b *= sc_b;
#pragma unroll
        for (int nt = 0; nt < 8; nt++) {
            o[nt][0] *= sc_a; o[nt][1] *= sc_a;
            o[nt][2] *= sc_b; o[nt][3] *= sc_b;
        }
        float sum_a = 0.f, sum_b = 0.f;
#pragma unroll
        for (int nt = 0; nt < 16; nt++) {
            s[nt][0] = __expf(s[nt][0] - nm_a);
            s[nt][1] = __expf(s[nt][1] - nm_a);
            s[nt][2] = __expf(s[nt][2] - nm_b);
            s[nt][3] = __expf(s[nt][3] - nm_b);
            sum_a += s[nt][0] + s[nt][1];
            sum_b += s[nt][2] + s[nt][3];
        }
        l_a += sum_a; l_b += sum_b;

        // ---- O += P V : 2-term split (drop V-lo) ----
#pragma unroll
        for (int ks = 0; ks < 8; ks++) {
            unsigned rah[4], ral[4];
            pack2(s[2*ks  ][0], s[2*ks  ][1], rah[0], ral[0]);
            pack2(s[2*ks  ][2], s[2*ks  ][3], rah[1], ral[1]);
            pack2(s[2*ks+1][0], s[2*ks+1][1], rah[2], ral[2]);
            pack2(s[2*ks+1][2], s[2*ks+1][3], rah[3], ral[3]);
#pragma unroll
            for (int nt = 0; nt < 8; nt++) {
                const int n = nt * 8 + g;
                unsigned w0 = Vc[(ks*16 + t2    ) * VS_ST + n];
                unsigned w1 = Vc[(ks*16 + t2 + 1) * VS_ST + n];
                unsigned w2 = Vc[(ks*16 + t2 + 8) * VS_ST + n];
                unsigned w3 = Vc[(ks*16 + t2 + 9) * VS_ST + n];
                unsigned bh[2];
                bh[0] = __byte_perm(w0, w1, 0x5410);
                bh[1] = __byte_perm(w2, w3, 0x5410);
                mma16816(o[nt], rah, bh);
                mma16816(o[nt], ral, bh);
            }
        }
    }

    l_a += __shfl_xor_sync(0xffffffffu, l_a, 1);
    l_a += __shfl_xor_sync(0xffffffffu, l_a, 2);
    l_b += __shfl_xor_sync(0xffffffffu, l_b, 1);
    l_b += __shfl_xor_sync(0xffffffffu, l_b, 2);
    const float inv_a = 1.f / l_a;
    const float inv_b = 1.f / l_b;

    const int row_a = m0 + wrow + g;
    const int row_b = row_a + 8;
#pragma unroll
    for (int nt = 0; nt < 8; nt++) {
        const int col = nt * 8 + t2;
        uint2 pa, pb;
        pa.x = pack_hl(o[nt][0] * inv_a); pa.y = pack_hl(o[nt][1] * inv_a);
        pb.x = pack_hl(o[nt][2] * inv_b); pb.y = pack_hl(o[nt][3] * inv_b);
        *(uint2*)&O[(long)row_a * ldo + col] = pa;
        *(uint2*)&O[(long)row_b * ldo + col] = pb;
    }
}

// ---------------- fp16-split tensor-core GEMM, cp.async 2-stage pipeline ----------------
// C[m,n] = sum_k A[m,k]*B[n,k], A/B packed (hi,lo) u32. 2-term: Ahi*Bhi + Alo*Bhi.
template<int BM, int BN, int BK, int WM, int WN, int ACT, bool OUTH>
__global__ void __launch_bounds__(256, 2)
mma_gemm(const unsigned* __restrict__ A, int lda,
         const unsigned* __restrict__ B, int ldb,
         void* __restrict__ Cv, int ldc,
         int K,
         const float* __restrict__ bias,
         const float* __restrict__ resid, int ldr)
{
    constexpr int AST   = BK + 8;                      // 40 u32: stride ≡ 8 (mod 32 banks)
    constexpr int BST   = BK + 8;
    constexpr int A_TILE = BM * AST;
    constexpr int B_TILE = BN * BST;
    constexpr int STAGE  = A_TILE + B_TILE;
    constexpr int NWN = BN / WN;
    constexpr int MT  = WM / 16;
    constexpr int NT  = WN / 8;

    extern __shared__ unsigned smu[];

    const int tid = threadIdx.x;
    const int wid = tid >> 5, lane = tid & 31;
    const int wm = wid / NWN, wn = wid % NWN;
    const int g  = lane >> 2, t2 = (lane & 3) * 2;

    const int m0 = blockIdx.y * BM, n0 = blockIdx.x * BN;

    float acc[MT][NT][4];
#pragma unroll
    for (int i = 0; i < MT; i++)
#pragma unroll
        for (int j = 0; j < NT; j++)
#pragma unroll
            for (int c = 0; c < 4; c++) acc[i][j][c] = 0.f;

    auto load_tiles = [&](int k0, int s){
        unsigned* Ad = smu + s * STAGE;
        unsigned* Bd = Ad + A_TILE;
        constexpr int ACH = BM * BK / 4;
#pragma unroll
        for (int idx = tid; idx < ACH; idx += 256) {
            const int r = idx / (BK / 4), c = idx % (BK / 4);
            cp16(&Ad[r * AST + c * 4], A + (long)(m0 + r) * lda + k0 + c * 4);
        }
        constexpr int BCH = BN * BK / 4;
#pragma unroll
        for (int idx = tid; idx < BCH; idx += 256) {
            const int r = idx / (BK / 4), c = idx % (BK / 4);
            cp16(&Bd[r * BST + c * 4], B + (long)(n0 + r) * ldb + k0 + c * 4);
        }
    };

    const int iters = K / BK;
    load_tiles(0, 0);
    CP_COMMIT();

    for (int it = 0; it < iters; it++) {
        if (it + 1 < iters) {
            load_tiles((it + 1) * BK, (it + 1) & 1);
            CP_COMMIT();
            CP_WAIT_1();
        } else {
            CP_WAIT_0();
        }
        __syncthreads();

        const unsigned* Ac = smu + (it & 1) * STAGE;
        const unsigned* Bc = Ac + A_TILE;

#pragma unroll
        for (int kk = 0; kk < BK; kk += 16) {
            unsigned rbh[NT][2];
#pragma unroll
            for (int nt = 0; nt < NT; nt++) {
                const int r = wn * WN + nt * 8 + g;
                uint2 v0 = *(const uint2*)&Bc[r * BST + kk + t2];
                uint2 v1 = *(const uint2*)&Bc[r * BST + kk + t2 + 8];
                rbh[nt][0] = __byte_perm(v0.x, v0.y, 0x5410);
                rbh[nt][1] = __byte_perm(v1.x, v1.y, 0x5410);
            }
#pragma unroll
            for (int mt = 0; mt < MT; mt++) {
                const int r = wm * WM + mt * 16 + g;
                uint2 a0 = *(const uint2*)&Ac[r       * AST + kk + t2];
                uint2 a1 = *(const uint2*)&Ac[(r + 8) * AST + kk + t2];
                uint2 a2 = *(const uint2*)&Ac[r       * AST + kk + t2 + 8];
                uint2 a3 = *(const uint2*)&Ac[(r + 8) * AST + kk + t2 + 8];
                unsigned rah[4], ral[4];
                rah[0] = __byte_perm(a0.x, a0.y, 0x5410);
                ral[0] = __byte_perm(a0.x, a0.y, 0x7632);
                rah[1] = __byte_perm(a1.x, a1.y, 0x5410);
                ral[1] = __byte_perm(a1.x, a1.y, 0x7632);
                rah[2] = __byte_perm(a2.x, a2.y, 0x5410);
                ral[2] = __byte_perm(a2.x, a2.y, 0x7632);
                rah[3] = __byte_perm(a3.x, a3.y, 0x5410);
                ral[3] = __byte_perm(a3.x, a3.y, 0x7632);
#pragma unroll
                for (int nt = 0; nt < NT; nt++) {
                    mma16816(acc[mt][nt], rah, rbh[nt]);
                    mma16816(acc[mt][nt], ral, rbh[nt]);
                }
            }
        }
        __syncthreads();
    }

    // ---------------- epilogue ----------------
#pragma unroll
    for (int mt = 0; mt < MT; mt++) {
#pragma unroll
        for (int nt = 0; nt < NT; nt++) {
            const int row0 = m0 + wm * WM + mt * 16 + g;
            const int col  = n0 + wn * WN + nt * 8 + t2;
#pragma unroll
            for (int half = 0; half < 2; half++) {
                const int row = row0 + half * 8;
                float v0 = acc[mt][nt][half * 2 + 0];
                float v1 = acc[mt][nt][half * 2 + 1];
                if (bias)  { v0 += bias[col]; v1 += bias[col + 1]; }
                if (resid) { v0 += resid[(long)row * ldr + col];
                             v1 += resid[(long)row * ldr + col + 1]; }
                if (ACT == 1) {
                    v0 = 0.5f * v0 * (1.0f + erff(v0 * 0.70710678118654752f));
                    v1 = 0.5f * v1 * (1.0f + erff(v1 * 0.70710678118654752f));
                }
                if (OUTH) {
                    uint2 w; w.x = pack_hl(v0); w.y = pack_hl(v1);
                    *(uint2*)((unsigned*)Cv + (long)row * ldc + col) = w;
                } else {
                    float2 w; w.x = v0; w.y = v1;
                    *(float2*)((float*)Cv + (long)row * ldc + col) = w;
                }
            }
        }
    }
}

// ---------------- launcher ----------------
extern "C" void kernel_launch(void* const* d_in, const int* in_sizes, int n_in,
                              void* d_out, int out_size)
{
    const float* q     = (const float*)d_in[0];
    const float* kv    = (const float*)d_in[1];
    const float* n1g   = (const float*)d_in[2];
    const float* n1b   = (const float*)d_in[3];
    const float* qkv_w = (const float*)d_in[4];
    const float* sa_pw = (const float*)d_in[5];
    const float* sa_pb = (const float*)d_in[6];
    const float* n2qg  = (const float*)d_in[7];
    const float* n2qb  = (const float*)d_in[8];
    const float* n2kg  = (const float*)d_in[9];
    const float* n2kb  = (const float*)d_in[10];
    const float* caq_w = (const float*)d_in[11];
    const float* cakv_w= (const float*)d_in[12];
    const float* cap_w = (const float*)d_in[13];
    const float* cap_b = (const float*)d_in[14];
    const float* n3g   = (const float*)d_in[15];
    const float* n3b   = (const float*)d_in[16];
    const float* fc1w  = (const float*)d_in[17];
    const float* fc1b  = (const float*)d_in[18];
    const float* fc2w  = (const float*)d_in[19];
    const float* fc2b  = (const float*)d_in[20];
    float* out = (float*)d_out;

    unsigned *x, *xkv, *qkvb, *attn, *qh, *kvp, *hid;
    unsigned *wqkv, *wsa, *wcaq, *wcakv, *wcap, *wfc1, *wfc2;
    float *q1, *q2;
    cudaGetSymbolAddress((void**)&x,    g_x);
    cudaGetSymbolAddress((void**)&xkv,  g_xkv);
    cudaGetSymbolAddress((void**)&qkvb, g_qkv);
    cudaGetSymbolAddress((void**)&attn, g_attn);
    cudaGetSymbolAddress((void**)&qh,   g_qh);
    cudaGetSymbolAddress((void**)&kvp,  g_kvp);
    cudaGetSymbolAddress((void**)&q1,   g_q1);
    cudaGetSymbolAddress((void**)&q2,   g_q2);
    cudaGetSymbolAddress((void**)&hid,  g_hid);
    cudaGetSymbolAddress((void**)&wqkv, g_wqkv);
    cudaGetSymbolAddress((void**)&wsa,  g_wsa);
    cudaGetSymbolAddress((void**)&wcaq, g_wcaq);
    cudaGetSymbolAddress((void**)&wcakv,g_wcakv);
    cudaGetSymbolAddress((void**)&wcap, g_wcap);
    cudaGetSymbolAddress((void**)&wfc1, g_wfc1);
    cudaGetSymbolAddress((void**)&wfc2, g_wfc2);

    const int SM_MAIN = (128*40 + 128*40) * 2 * 4;   // 81920 B
    cudaFuncSetAttribute(mma_gemm<128,128,32,64,32,0,true>,
                         cudaFuncAttributeMaxDynamicSharedMemorySize, SM_MAIN);
    cudaFuncSetAttribute(mma_gemm<128,128,32,64,32,0,false>,
                         cudaFuncAttributeMaxDynamicSharedMemorySize, SM_MAIN);
    cudaFuncSetAttribute(mma_gemm<128,128,32,64,32,1,true>,
                         cudaFuncAttributeMaxDynamicSharedMemorySize, SM_MAIN);
    cudaFuncSetAttribute(flash_kernel,
                         cudaFuncAttributeMaxDynamicSharedMemorySize, FLASH_SMEM);

    const dim3 blk(256);
    const long QKV_B = (long)LQn * 3 * Dm;
    const long TOK_B = (long)LQn * Dm;
    const long KVP_B = (long)LKVn * 2 * Dm;

    // ---- weight conversion (merged) ----
    {
        CvtArgs a;
        a.s[0]=qkv_w;  a.d[0]=wqkv;  a.n[0]=3*Dm*Dm;
        a.s[1]=sa_pw;  a.d[1]=wsa;   a.n[1]=Dm*Dm;
        a.s[2]=caq_w;  a.d[2]=wcaq;  a.n[2]=Dm*Dm;
        a.s[3]=cakv_w; a.d[3]=wcakv; a.n[3]=2*Dm*Dm;
        a.s[4]=cap_w;  a.d[4]=wcap;  a.n[4]=Dm*Dm;
        a.s[5]=fc1w;   a.d[5]=wfc1;  a.n[5]=HIDn*Dm;
        a.s[6]=fc2w;   a.d[6]=wfc2;  a.n[6]=Dm*HIDn;
        cvt_all<<<dim3((HIDn*Dm + 255)/256, 7), 256>>>(a);
    }

    // ===== self-attention =====
    ln_kernel<<<NTOK, 256>>>(q, n1g, n1b, x);

    mma_gemm<128,128,32,64,32,0,true><<<dim3(3*Dm/128, NTOK/128), blk, SM_MAIN>>>(
        x, Dm, wqkv, Dm, qkvb, 3*Dm, Dm, nullptr, nullptr, 0);

    flash_kernel<<<dim3(LQn/128, Bq*Hn), blk, FLASH_SMEM>>>(
        qkvb,        3*Dm, QKV_B,
        qkvb + Dm,   3*Dm, QKV_B,
        qkvb + 2*Dm, 3*Dm, QKV_B,
        attn, Dm, TOK_B);

    mma_gemm<128,128,32,64,32,0,false><<<dim3(Dm/128, NTOK/128), blk, SM_MAIN>>>(
        attn, Dm, wsa, Dm, q1, Dm, Dm, sa_pb, q, Dm);

    // ===== cross-attention =====
    ln_kernel<<<NTOK, 256>>>(q1, n2qg, n2qb, x);
    ln_kernel<<<NTOK, 256>>>(kv, n2kg, n2kb, xkv);

    mma_gemm<128,128,32,64,32,0,true><<<dim3(Dm/128, NTOK/128), blk, SM_MAIN>>>(
        x, Dm, wcaq, Dm, qh, Dm, Dm, nullptr, nullptr, 0);

    mma_gemm<128,128,32,64,32,0,true><<<dim3(2*Dm/128, NTOK/128), blk, SM_MAIN>>>(
        xkv, Dm, wcakv, Dm, kvp, 2*Dm, Dm, nullptr, nullptr, 0);

    flash_kernel<<<dim3(LQn/128, Bq*Hn), blk, FLASH_SMEM>>>(
        qh,        Dm,   TOK_B,
        kvp,       2*Dm, KVP_B,
        kvp + Dm,  2*Dm, KVP_B,
        attn, Dm, TOK_B);

    mma_gemm<128,128,32,64,32,0,false><<<dim3(Dm/128, NTOK/128), blk, SM_MAIN>>>(
        attn, Dm, wcap, Dm, q2, Dm, Dm, cap_b, q1, Dm);

    // ===== MLP =====
    ln_kernel<<<NTOK, 256>>>(q2, n3g, n3b, x);

    mma_gemm<128,128,32,64,32,1,true><<<dim3(HIDn/128, NTOK/128), blk, SM_MAIN>>>(
        x, Dm, wfc1, Dm, hid, HIDn, Dm, fc1b, nullptr, 0);

    mma_gemm<128,128,32,64,32,0,false><<<dim3(Dm/128, NTOK/128), blk, SM_MAIN>>>(
        hid, HIDn, wfc2, HIDn, out, Dm, HIDn, fc2b, q2, Dm);
}

// round 9
// speedup vs baseline: 2.2824x; 1.5404x over previous
#include <cuda_runtime.h>
#include <cuda_fp16.h>
#include <math.h>

// ---------------- problem constants ----------------
#define Bq   16
#define LQn  512
#define LKVn 512
#define Dm   768
#define Hn   12
#define HDn  64
#define HIDn 3072
#define NTOK (Bq*LQn)          // 8192

// ---------------- scratch (device globals, plain fp16) ----------------
__device__ __align__(16) __half g_x   [NTOK*Dm];
__device__ __align__(16) __half g_xkv [NTOK*Dm];
__device__ __align__(16) __half g_qkv [NTOK*3*Dm];
__device__ __align__(16) __half g_attn[NTOK*Dm];
__device__ __align__(16) __half g_qh  [NTOK*Dm];
__device__ __align__(16) __half g_kvp [NTOK*2*Dm];
__device__ float  g_q1  [NTOK*Dm];
__device__ float  g_q2  [NTOK*Dm];
__device__ __align__(16) __half g_hid [NTOK*HIDn];
// converted weights
__device__ __align__(16) __half g_wqkv [3*Dm*Dm];
__device__ __align__(16) __half g_wsa  [Dm*Dm];
__device__ __align__(16) __half g_wcaq [Dm*Dm];
__device__ __align__(16) __half g_wcakv[2*Dm*Dm];
__device__ __align__(16) __half g_wcap [Dm*Dm];
__device__ __align__(16) __half g_wfc1 [HIDn*Dm];
__device__ __align__(16) __half g_wfc2 [Dm*HIDn];

// ---------------- helpers ----------------
__device__ __forceinline__ float warp_sum(float v){
#pragma unroll
    for (int o = 16; o > 0; o >>= 1) v += __shfl_xor_sync(0xffffffffu, v, o);
    return v;
}

__device__ __forceinline__ void mma16816(float* c, const unsigned* a, const unsigned* b){
    asm volatile(
        "mma.sync.aligned.m16n8k16.row.col.f32.f16.f16.f32 "
        "{%0,%1,%2,%3},{%4,%5,%6,%7},{%8,%9},{%0,%1,%2,%3};"
        : "+f"(c[0]), "+f"(c[1]), "+f"(c[2]), "+f"(c[3])
        : "r"(a[0]), "r"(a[1]), "r"(a[2]), "r"(a[3]), "r"(b[0]), "r"(b[1]));
}

__device__ __forceinline__ void cp16(void* smem_dst, const void* gsrc){
    unsigned s = (unsigned)__cvta_generic_to_shared(smem_dst);
    asm volatile("cp.async.cg.shared.global [%0], [%1], 16;\n" :: "r"(s), "l"(gsrc));
}
#define CP_COMMIT()  asm volatile("cp.async.commit_group;\n" ::: "memory")
#define CP_WAIT_1()  asm volatile("cp.async.wait_group 1;\n" ::: "memory")
#define CP_WAIT_0()  asm volatile("cp.async.wait_group 0;\n" ::: "memory")

// pack two fp32 into f16x2 register (low16 = p0)
__device__ __forceinline__ unsigned packf2(float p0, float p1){
    unsigned r;
    asm("cvt.rn.f16x2.f32 %0, %1, %2;" : "=r"(r) : "f"(p1), "f"(p0));
    return r;
}

// ---------------- merged weight conversion (blockIdx.y = segment) ----------------
struct CvtArgs {
    const float* s[7];
    __half*      d[7];
    int          n[7];
};
__global__ void cvt_all(CvtArgs a){
    const int seg = blockIdx.y;
    const int i = blockIdx.x * 256 + threadIdx.x;
    if (i < a.n[seg]) a.d[seg][i] = __float2half_rn(a.s[seg][i]);
}

// ---------------- LayerNorm -> fp16 ----------------
__global__ void ln_kernel(const float* __restrict__ x, const float* __restrict__ g,
                          const float* __restrict__ b, __half* __restrict__ y)
{
    __shared__ float sh[8];
    const long row = blockIdx.x;
    const float* xr = x + row * Dm;
    __half* yr = y + row * Dm;
    const int tid = threadIdx.x;
    const int w = tid >> 5, l = tid & 31;

    float v0 = xr[tid], v1 = xr[tid + 256], v2 = xr[tid + 512];

    float s = warp_sum(v0 + v1 + v2);
    if (l == 0) sh[w] = s;
    __syncthreads();
    if (w == 0) { float t = (l < 8) ? sh[l] : 0.f; t = warp_sum(t); if (l == 0) sh[0] = t; }
    __syncthreads();
    const float mean = sh[0] * (1.f / 768.f);
    __syncthreads();

    const float d0 = v0 - mean, d1 = v1 - mean, d2 = v2 - mean;
    float s2 = warp_sum(d0*d0 + d1*d1 + d2*d2);
    if (l == 0) sh[w] = s2;
    __syncthreads();
    if (w == 0) { float t = (l < 8) ? sh[l] : 0.f; t = warp_sum(t); if (l == 0) sh[0] = t; }
    __syncthreads();
    const float inv = rsqrtf(sh[0] * (1.f / 768.f) + 1e-5f);

    yr[tid]       = __float2half_rn(d0 * inv * g[tid]       + b[tid]);
    yr[tid + 256] = __float2half_rn(d1 * inv * g[tid + 256] + b[tid + 256]);
    yr[tid + 512] = __float2half_rn(d2 * inv * g[tid + 512] + b[tid + 512]);
}

// ---------------- fused flash attention (fp16 in/out, 128 Q-rows x 512 keys) ----------------
#define QS_ST 72
#define KS_ST 72
#define VS_ST 72
#define Q_TILE (128*QS_ST)   // halves
#define K_TILE (128*KS_ST)
#define V_TILE (128*VS_ST)
#define FLASH_SMEM ((Q_TILE + 2*K_TILE + 2*V_TILE) * 2)   // 92160 B

__global__ void __launch_bounds__(256, 1)
flash_kernel(const __half* __restrict__ Q, int ldq, long Qb,
             const __half* __restrict__ K, int ldk, long Kb,
             const __half* __restrict__ V, int ldv, long Vb,
             __half* __restrict__ O, int ldo, long Ob)
{
    extern __shared__ __half smh[];
    __half* Qs = smh;
    __half* Ks = smh + Q_TILE;
    __half* Vs = smh + Q_TILE + 2*K_TILE;

    const int tid  = threadIdx.x;
    const int wid  = tid >> 5, lane = tid & 31;
    const int g    = lane >> 2, t2 = (lane & 3) * 2;
    const int m0   = blockIdx.x * 128;
    const int wrow = wid * 16;

    {
        const int z = blockIdx.y;
        const int bb = z / Hn, hh = z - bb * Hn;
        Q += (long)bb * Qb + hh * 64;
        K += (long)bb * Kb + hh * 64;
        V += (long)bb * Vb + hh * 64;
        O += (long)bb * Ob + hh * 64;
    }

    // loaders: 128 rows x 64 halves = 8 chunks of 16B per row
    auto loadQ = [&](){
#pragma unroll
        for (int idx = tid; idx < 1024; idx += 256) {
            const int r = idx >> 3, c = idx & 7;
            cp16(&Qs[r * QS_ST + c * 8], Q + (long)(m0 + r) * ldq + c * 8);
        }
    };
    auto loadK = [&](int kt, int s){
        __half* dst = Ks + s * K_TILE;
#pragma unroll
        for (int idx = tid; idx < 1024; idx += 256) {
            const int r = idx >> 3, c = idx & 7;
            cp16(&dst[r * KS_ST + c * 8], K + (long)(kt * 128 + r) * ldk + c * 8);
        }
    };
    auto loadV = [&](int kt, int s){
        __half* dst = Vs + s * V_TILE;
#pragma unroll
        for (int idx = tid; idx < 1024; idx += 256) {
            const int r = idx >> 3, c = idx & 7;
            cp16(&dst[r * VS_ST + c * 8], V + (long)(kt * 128 + r) * ldv + c * 8);
        }
    };

    float o[8][4];
#pragma unroll
    for (int i = 0; i < 8; i++)
#pragma unroll
        for (int j = 0; j < 4; j++) o[i][j] = 0.f;
    float m_a = -1e30f, m_b = -1e30f, l_a = 0.f, l_b = 0.f;

    loadQ(); loadK(0, 0); loadV(0, 0); CP_COMMIT();
    loadK(1, 1); loadV(1, 1); CP_COMMIT();

    for (int it = 0; it < 4; it++) {
        if (it >= 1) {
            __syncthreads();
            if (it + 1 < 4) { loadK(it + 1, (it + 1) & 1); loadV(it + 1, (it + 1) & 1); CP_COMMIT(); }
        }
        if (it + 1 < 4) CP_WAIT_1(); else CP_WAIT_0();
        __syncthreads();

        const __half* Kc = Ks + (it & 1) * K_TILE;
        const __half* Vc = Vs + (it & 1) * V_TILE;

        // ---- S = Q K^T ----
        float s[16][4];
#pragma unroll
        for (int nt = 0; nt < 16; nt++)
#pragma unroll
            for (int c = 0; c < 4; c++) s[nt][c] = 0.f;

#pragma unroll
        for (int kk = 0; kk < 64; kk += 16) {
            const int r = wrow + g;
            unsigned ra[4];
            ra[0] = *(const unsigned*)&Qs[r       * QS_ST + kk + t2];
            ra[1] = *(const unsigned*)&Qs[(r + 8) * QS_ST + kk + t2];
            ra[2] = *(const unsigned*)&Qs[r       * QS_ST + kk + t2 + 8];
            ra[3] = *(const unsigned*)&Qs[(r + 8) * QS_ST + kk + t2 + 8];
#pragma unroll
            for (int nt = 0; nt < 16; nt++) {
                const int kr = nt * 8 + g;
                unsigned rb[2];
                rb[0] = *(const unsigned*)&Kc[kr * KS_ST + kk + t2];
                rb[1] = *(const unsigned*)&Kc[kr * KS_ST + kk + t2 + 8];
                mma16816(s[nt], ra, rb);
            }
        }

        // ---- online softmax (scale 1/8 folded) ----
        float mx_a = -1e30f, mx_b = -1e30f;
#pragma unroll
        for (int nt = 0; nt < 16; nt++) {
#pragma unroll
            for (int c = 0; c < 4; c++) s[nt][c] *= 0.125f;
            mx_a = fmaxf(mx_a, fmaxf(s[nt][0], s[nt][1]));
            mx_b = fmaxf(mx_b, fmaxf(s[nt][2], s[nt][3]));
        }
        mx_a = fmaxf(mx_a, __shfl_xor_sync(0xffffffffu, mx_a, 1));
        mx_a = fmaxf(mx_a, __shfl_xor_sync(0xffffffffu, mx_a, 2));
        mx_b = fmaxf(mx_b, __shfl_xor_sync(0xffffffffu, mx_b, 1));
        mx_b = fmaxf(mx_b, __shfl_xor_sync(0xffffffffu, mx_b, 2));

        const float nm_a = fmaxf(m_a, mx_a);
        const float nm_b = fmaxf(m_b, mx_b);
        const float sc_a = __expf(m_a - nm_a);
        const float sc_b = __expf(m_b - nm_b);
        m_a = nm_a; m_b = nm_b;
        l_a *= sc_a; l_b *= sc_b;
#pragma unroll
        for (int nt = 0; nt < 8; nt++) {
            o[nt][0] *= sc_a; o[nt][1] *= sc_a;
            o[nt][2] *= sc_b; o[nt][3] *= sc_b;
        }
        float sum_a = 0.f, sum_b = 0.f;
#pragma unroll
        for (int nt = 0; nt < 16; nt++) {
            s[nt][0] = __expf(s[nt][0] - nm_a);
            s[nt][1] = __expf(s[nt][1] - nm_a);
            s[nt][2] = __expf(s[nt][2] - nm_b);
            s[nt][3] = __expf(s[nt][3] - nm_b);
            sum_a += s[nt][0] + s[nt][1];
            sum_b += s[nt][2] + s[nt][3];
        }
        l_a += sum_a; l_b += sum_b;

        // ---- O += P V ----
        const unsigned short* Vu = (const unsigned short*)Vc;
#pragma unroll
        for (int ks = 0; ks < 8; ks++) {
            unsigned ra[4];
            ra[0] = packf2(s[2*ks  ][0], s[2*ks  ][1]);
            ra[1] = packf2(s[2*ks  ][2], s[2*ks  ][3]);
            ra[2] = packf2(s[2*ks+1][0], s[2*ks+1][1]);
            ra[3] = packf2(s[2*ks+1][2], s[2*ks+1][3]);
            const int r0 = ks * 16 + t2;
#pragma unroll
            for (int nt = 0; nt < 8; nt++) {
                const int n = nt * 8 + g;
                unsigned b0 = (unsigned)Vu[(r0    ) * VS_ST + n]
                            | ((unsigned)Vu[(r0 + 1) * VS_ST + n] << 16);
                unsigned b1 = (unsigned)Vu[(r0 + 8) * VS_ST + n]
                            | ((unsigned)Vu[(r0 + 9) * VS_ST + n] << 16);
                unsigned rb[2] = {b0, b1};
                mma16816(o[nt], ra, rb);
            }
        }
    }

    l_a += __shfl_xor_sync(0xffffffffu, l_a, 1);
    l_a += __shfl_xor_sync(0xffffffffu, l_a, 2);
    l_b += __shfl_xor_sync(0xffffffffu, l_b, 1);
    l_b += __shfl_xor_sync(0xffffffffu, l_b, 2);
    const float inv_a = 1.f / l_a;
    const float inv_b = 1.f / l_b;

    const int row_a = m0 + wrow + g;
    const int row_b = row_a + 8;
#pragma unroll
    for (int nt = 0; nt < 8; nt++) {
        const int col = nt * 8 + t2;
        *(unsigned*)&O[(long)row_a * ldo + col] = packf2(o[nt][0] * inv_a, o[nt][1] * inv_a);
        *(unsigned*)&O[(long)row_b * ldo + col] = packf2(o[nt][2] * inv_b, o[nt][3] * inv_b);
    }
}

// ---------------- fp16 tensor-core GEMM, cp.async 2-stage pipeline ----------------
// C[m,n] = sum_k A[m,k]*B[n,k]. ACT==1: exact GELU. OUTH: fp16 out else fp32 (+bias/resid).
template<int BM, int BN, int BK, int WM, int WN, int ACT, bool OUTH>
__global__ void __launch_bounds__(256, 2)
mma_gemm(const __half* __restrict__ A, int lda,
         const __half* __restrict__ B, int ldb,
         void* __restrict__ Cv, int ldc,
         int K,
         const float* __restrict__ bias,
         const float* __restrict__ resid, int ldr)
{
    constexpr int AST   = BK + 8;                      // 40 halves (80 B)
    constexpr int BST   = BK + 8;
    constexpr int A_TILE = BM * AST;                   // halves
    constexpr int B_TILE = BN * BST;
    constexpr int STAGE  = A_TILE + B_TILE;
    constexpr int NWN = BN / WN;
    constexpr int MT  = WM / 16;
    constexpr int NT  = WN / 8;

    extern __shared__ __half smh[];

    const int tid = threadIdx.x;
    const int wid = tid >> 5, lane = tid & 31;
    const int wm = wid / NWN, wn = wid % NWN;
    const int g  = lane >> 2, t2 = (lane & 3) * 2;

    const int m0 = blockIdx.y * BM, n0 = blockIdx.x * BN;

    float acc[MT][NT][4];
#pragma unroll
    for (int i = 0; i < MT; i++)
#pragma unroll
        for (int j = 0; j < NT; j++)
#pragma unroll
            for (int c = 0; c < 4; c++) acc[i][j][c] = 0.f;

    auto load_tiles = [&](int k0, int s){
        __half* Ad = smh + s * STAGE;
        __half* Bd = Ad + A_TILE;
        constexpr int ACH = BM * BK / 8;               // 16B chunks
#pragma unroll
        for (int idx = tid; idx < ACH; idx += 256) {
            const int r = idx / (BK / 8), c = idx % (BK / 8);
            cp16(&Ad[r * AST + c * 8], A + (long)(m0 + r) * lda + k0 + c * 8);
        }
        constexpr int BCH = BN * BK / 8;
#pragma unroll
        for (int idx = tid; idx < BCH; idx += 256) {
            const int r = idx / (BK / 8), c = idx % (BK / 8);
            cp16(&Bd[r * BST + c * 8], B + (long)(n0 + r) * ldb + k0 + c * 8);
        }
    };

    const int iters = K / BK;
    load_tiles(0, 0);
    CP_COMMIT();

    for (int it = 0; it < iters; it++) {
        if (it + 1 < iters) {
            load_tiles((it + 1) * BK, (it + 1) & 1);
            CP_COMMIT();
            CP_WAIT_1();
        } else {
            CP_WAIT_0();
        }
        __syncthreads();

        const __half* Ac = smh + (it & 1) * STAGE;
        const __half* Bc = Ac + A_TILE;

#pragma unroll
        for (int kk = 0; kk < BK; kk += 16) {
            unsigned rb[NT][2];
#pragma unroll
            for (int nt = 0; nt < NT; nt++) {
                const int r = wn * WN + nt * 8 + g;
                rb[nt][0] = *(const unsigned*)&Bc[r * BST + kk + t2];
                rb[nt][1] = *(const unsigned*)&Bc[r * BST + kk + t2 + 8];
            }
#pragma unroll
            for (int mt = 0; mt < MT; mt++) {
                const int r = wm * WM + mt * 16 + g;
                unsigned ra[4];
                ra[0] = *(const unsigned*)&Ac[r       * AST + kk + t2];
                ra[1] = *(const unsigned*)&Ac[(r + 8) * AST + kk + t2];
                ra[2] = *(const unsigned*)&Ac[r       * AST + kk + t2 + 8];
                ra[3] = *(const unsigned*)&Ac[(r + 8) * AST + kk + t2 + 8];
#pragma unroll
                for (int nt = 0; nt < NT; nt++)
                    mma16816(acc[mt][nt], ra, rb[nt]);
            }
        }
        __syncthreads();
    }

    // ---------------- epilogue ----------------
#pragma unroll
    for (int mt = 0; mt < MT; mt++) {
#pragma unroll
        for (int nt = 0; nt < NT; nt++) {
            const int row0 = m0 + wm * WM + mt * 16 + g;
            const int col  = n0 + wn * WN + nt * 8 + t2;
#pragma unroll
            for (int half = 0; half < 2; half++) {
                const int row = row0 + half * 8;
                float v0 = acc[mt][nt][half * 2 + 0];
                float v1 = acc[mt][nt][half * 2 + 1];
                if (bias)  { v0 += bias[col]; v1 += bias[col + 1]; }
                if (resid) { v0 += resid[(long)row * ldr + col];
                             v1 += resid[(long)row * ldr + col + 1]; }
                if (ACT == 1) {
                    v0 = 0.5f * v0 * (1.0f + erff(v0 * 0.70710678118654752f));
                    v1 = 0.5f * v1 * (1.0f + erff(v1 * 0.70710678118654752f));
                }
                if (OUTH) {
                    *(unsigned*)((__half*)Cv + (long)row * ldc + col) = packf2(v0, v1);
                } else {
                    float2 w; w.x = v0; w.y = v1;
                    *(float2*)((float*)Cv + (long)row * ldc + col) = w;
                }
            }
        }
    }
}

// ---------------- launcher ----------------
extern "C" void kernel_launch(void* const* d_in, const int* in_sizes, int n_in,
                              void* d_out, int out_size)
{
    const float* q     = (const float*)d_in[0];
    const float* kv    = (const float*)d_in[1];
    const float* n1g   = (const float*)d_in[2];
    const float* n1b   = (const float*)d_in[3];
    const float* qkv_w = (const float*)d_in[4];
    const float* sa_pw = (const float*)d_in[5];
    const float* sa_pb = (const float*)d_in[6];
    const float* n2qg  = (const float*)d_in[7];
    const float* n2qb  = (const float*)d_in[8];
    const float* n2kg  = (const float*)d_in[9];
    const float* n2kb  = (const float*)d_in[10];
    const float* caq_w = (const float*)d_in[11];
    const float* cakv_w= (const float*)d_in[12];
    const float* cap_w = (const float*)d_in[13];
    const float* cap_b = (const float*)d_in[14];
    const float* n3g   = (const float*)d_in[15];
    const float* n3b   = (const float*)d_in[16];
    const float* fc1w  = (const float*)d_in[17];
    const float* fc1b  = (const float*)d_in[18];
    const float* fc2w  = (const float*)d_in[19];
    const float* fc2b  = (const float*)d_in[20];
    float* out = (float*)d_out;

    __half *x, *xkv, *qkvb, *attn, *qh, *kvp, *hid;
    __half *wqkv, *wsa, *wcaq, *wcakv, *wcap, *wfc1, *wfc2;
    float *q1, *q2;
    cudaGetSymbolAddress((void**)&x,    g_x);
    cudaGetSymbolAddress((void**)&xkv,  g_xkv);
    cudaGetSymbolAddress((void**)&qkvb, g_qkv);
    cudaGetSymbolAddress((void**)&attn, g_attn);
    cudaGetSymbolAddress((void**)&qh,   g_qh);
    cudaGetSymbolAddress((void**)&kvp,  g_kvp);
    cudaGetSymbolAddress((void**)&q1,   g_q1);
    cudaGetSymbolAddress((void**)&q2,   g_q2);
    cudaGetSymbolAddress((void**)&hid,  g_hid);
    cudaGetSymbolAddress((void**)&wqkv, g_wqkv);
    cudaGetSymbolAddress((void**)&wsa,  g_wsa);
    cudaGetSymbolAddress((void**)&wcaq, g_wcaq);
    cudaGetSymbolAddress((void**)&wcakv,g_wcakv);
    cudaGetSymbolAddress((void**)&wcap, g_wcap);
    cudaGetSymbolAddress((void**)&wfc1, g_wfc1);
    cudaGetSymbolAddress((void**)&wfc2, g_wfc2);

    const int SM_MAIN = (128*40 + 128*40) * 2 * 2;   // 40960 B
    cudaFuncSetAttribute(mma_gemm<128,128,32,64,32,0,true>,
                         cudaFuncAttributeMaxDynamicSharedMemorySize, SM_MAIN);
    cudaFuncSetAttribute(mma_gemm<128,128,32,64,32,0,false>,
                         cudaFuncAttributeMaxDynamicSharedMemorySize, SM_MAIN);
    cudaFuncSetAttribute(mma_gemm<128,128,32,64,32,1,true>,
                         cudaFuncAttributeMaxDynamicSharedMemorySize, SM_MAIN);
    cudaFuncSetAttribute(flash_kernel,
                         cudaFuncAttributeMaxDynamicSharedMemorySize, FLASH_SMEM);

    const dim3 blk(256);
    const long QKV_B = (long)LQn * 3 * Dm;
    const long TOK_B = (long)LQn * Dm;
    const long KVP_B = (long)LKVn * 2 * Dm;

    // ---- weight conversion (merged) ----
    {
        CvtArgs a;
        a.s[0]=qkv_w;  a.d[0]=wqkv;  a.n[0]=3*Dm*Dm;
        a.s[1]=sa_pw;  a.d[1]=wsa;   a.n[1]=Dm*Dm;
        a.s[2]=caq_w;  a.d[2]=wcaq;  a.n[2]=Dm*Dm;
        a.s[3]=cakv_w; a.d[3]=wcakv; a.n[3]=2*Dm*Dm;
        a.s[4]=cap_w;  a.d[4]=wcap;  a.n[4]=Dm*Dm;
        a.s[5]=fc1w;   a.d[5]=wfc1;  a.n[5]=HIDn*Dm;
        a.s[6]=fc2w;   a.d[6]=wfc2;  a.n[6]=Dm*HIDn;
        cvt_all<<<dim3((HIDn*Dm + 255)/256, 7), 256>>>(a);
    }

    // ===== self-attention =====
    ln_kernel<<<NTOK, 256>>>(q, n1g, n1b, x);

    mma_gemm<128,128,32,64,32,0,true><<<dim3(3*Dm/128, NTOK/128), blk, SM_MAIN>>>(
        x, Dm, wqkv, Dm, qkvb, 3*Dm, Dm, nullptr, nullptr, 0);

    flash_kernel<<<dim3(LQn/128, Bq*Hn), blk, FLASH_SMEM>>>(
        qkvb,        3*Dm, QKV_B,
        qkvb + Dm,   3*Dm, QKV_B,
        qkvb + 2*Dm, 3*Dm, QKV_B,
        attn, Dm, TOK_B);

    mma_gemm<128,128,32,64,32,0,false><<<dim3(Dm/128, NTOK/128), blk, SM_MAIN>>>(
        attn, Dm, wsa, Dm, q1, Dm, Dm, sa_pb, q, Dm);

    // ===== cross-attention =====
    ln_kernel<<<NTOK, 256>>>(q1, n2qg, n2qb, x);
    ln_kernel<<<NTOK, 256>>>(kv, n2kg, n2kb, xkv);

    mma_gemm<128,128,32,64,32,0,true><<<dim3(Dm/128, NTOK/128), blk, SM_MAIN>>>(
        x, Dm, wcaq, Dm, qh, Dm, Dm, nullptr, nullptr, 0);

    mma_gemm<128,128,32,64,32,0,true><<<dim3(2*Dm/128, NTOK/128), blk, SM_MAIN>>>(
        xkv, Dm, wcakv, Dm, kvp, 2*Dm, Dm, nullptr, nullptr, 0);

    flash_kernel<<<dim3(LQn/128, Bq*Hn), blk, FLASH_SMEM>>>(
        qh,        Dm,   TOK_B,
        kvp,       2*Dm, KVP_B,
        kvp + Dm,  2*Dm, KVP_B,
        attn, Dm, TOK_B);

    mma_gemm<128,128,32,64,32,0,false><<<dim3(Dm/128, NTOK/128), blk, SM_MAIN>>>(
        attn, Dm, wcap, Dm, q2, Dm, Dm, cap_b, q1, Dm);

    // ===== MLP =====
    ln_kernel<<<NTOK, 256>>>(q2, n3g, n3b, x);

    mma_gemm<128,128,32,64,32,1,true><<<dim3(HIDn/128, NTOK/128), blk, SM_MAIN>>>(
        x, Dm, wfc1, Dm, hid, HIDn, Dm, fc1b, nullptr, 0);

    mma_gemm<128,128,32,64,32,0,false><<<dim3(Dm/128, NTOK/128), blk, SM_MAIN>>>(
        hid, HIDn, wfc2, HIDn, out, Dm, HIDn, fc2b, q2, Dm);
}

// round 10
// speedup vs baseline: 2.2976x; 1.0066x over previous
#include <cuda_runtime.h>
#include <cuda_fp16.h>
#include <math.h>

// ---------------- problem constants ----------------
#define Bq   16
#define LQn  512
#define LKVn 512
#define Dm   768
#define Hn   12
#define HDn  64
#define HIDn 3072
#define NTOK (Bq*LQn)          // 8192

// ---------------- scratch (device globals, plain fp16) ----------------
__device__ __align__(16) __half g_x   [NTOK*Dm];
__device__ __align__(16) __half g_xkv [NTOK*Dm];
__device__ __align__(16) __half g_qkv [NTOK*3*Dm];
__device__ __align__(16) __half g_attn[NTOK*Dm];
__device__ __align__(16) __half g_qh  [NTOK*Dm];
__device__ __align__(16) __half g_kvp [NTOK*2*Dm];
__device__ float  g_q1  [NTOK*Dm];
__device__ float  g_q2  [NTOK*Dm];
__device__ __align__(16) __half g_hid [NTOK*HIDn];
// converted weights
__device__ __align__(16) __half g_wqkv [3*Dm*Dm];
__device__ __align__(16) __half g_wsa  [Dm*Dm];
__device__ __align__(16) __half g_wcaq [Dm*Dm];
__device__ __align__(16) __half g_wcakv[2*Dm*Dm];
__device__ __align__(16) __half g_wcap [Dm*Dm];
__device__ __align__(16) __half g_wfc1 [HIDn*Dm];
__device__ __align__(16) __half g_wfc2 [Dm*HIDn];

// ---------------- helpers ----------------
__device__ __forceinline__ float warp_sum(float v){
#pragma unroll
    for (int o = 16; o > 0; o >>= 1) v += __shfl_xor_sync(0xffffffffu, v, o);
    return v;
}

__device__ __forceinline__ void mma16816(float* c, const unsigned* a, const unsigned* b){
    asm volatile(
        "mma.sync.aligned.m16n8k16.row.col.f32.f16.f16.f32 "
        "{%0,%1,%2,%3},{%4,%5,%6,%7},{%8,%9},{%0,%1,%2,%3};"
        : "+f"(c[0]), "+f"(c[1]), "+f"(c[2]), "+f"(c[3])
        : "r"(a[0]), "r"(a[1]), "r"(a[2]), "r"(a[3]), "r"(b[0]), "r"(b[1]));
}

__device__ __forceinline__ void cp16(void* smem_dst, const void* gsrc){
    unsigned s = (unsigned)__cvta_generic_to_shared(smem_dst);
    asm volatile("cp.async.cg.shared.global [%0], [%1], 16;\n" :: "r"(s), "l"(gsrc));
}
#define CP_COMMIT()  asm volatile("cp.async.commit_group;\n" ::: "memory")
#define CP_WAIT_2()  asm volatile("cp.async.wait_group 2;\n" ::: "memory")
#define CP_WAIT_1()  asm volatile("cp.async.wait_group 1;\n" ::: "memory")
#define CP_WAIT_0()  asm volatile("cp.async.wait_group 0;\n" ::: "memory")

// pack two fp32 into f16x2 register (low16 = p0)
__device__ __forceinline__ unsigned packf2(float p0, float p1){
    unsigned r;
    asm("cvt.rn.f16x2.f32 %0, %1, %2;" : "=r"(r) : "f"(p1), "f"(p0));
    return r;
}

// ---------------- merged weight conversion (blockIdx.y = segment) ----------------
struct CvtArgs {
    const float* s[7];
    __half*      d[7];
    int          n[7];
};
__global__ void cvt_all(CvtArgs a){
    const int seg = blockIdx.y;
    const int i = blockIdx.x * 256 + threadIdx.x;
    if (i < a.n[seg]) a.d[seg][i] = __float2half_rn(a.s[seg][i]);
}

// ---------------- LayerNorm -> fp16 ----------------
__global__ void ln_kernel(const float* __restrict__ x, const float* __restrict__ g,
                          const float* __restrict__ b, __half* __restrict__ y)
{
    __shared__ float sh[8];
    const long row = blockIdx.x;
    const float* xr = x + row * Dm;
    __half* yr = y + row * Dm;
    const int tid = threadIdx.x;
    const int w = tid >> 5, l = tid & 31;

    float v0 = xr[tid], v1 = xr[tid + 256], v2 = xr[tid + 512];

    float s = warp_sum(v0 + v1 + v2);
    if (l == 0) sh[w] = s;
    __syncthreads();
    if (w == 0) { float t = (l < 8) ? sh[l] : 0.f; t = warp_sum(t); if (l == 0) sh[0] = t; }
    __syncthreads();
    const float mean = sh[0] * (1.f / 768.f);
    __syncthreads();

    const float d0 = v0 - mean, d1 = v1 - mean, d2 = v2 - mean;
    float s2 = warp_sum(d0*d0 + d1*d1 + d2*d2);
    if (l == 0) sh[w] = s2;
    __syncthreads();
    if (w == 0) { float t = (l < 8) ? sh[l] : 0.f; t = warp_sum(t); if (l == 0) sh[0] = t; }
    __syncthreads();
    const float inv = rsqrtf(sh[0] * (1.f / 768.f) + 1e-5f);

    yr[tid]       = __float2half_rn(d0 * inv * g[tid]       + b[tid]);
    yr[tid + 256] = __float2half_rn(d1 * inv * g[tid + 256] + b[tid + 256]);
    yr[tid + 512] = __float2half_rn(d2 * inv * g[tid + 512] + b[tid + 512]);
}

// ---------------- fused flash attention (fp16 in/out, 128 Q-rows x 512 keys) ----------------
#define QS_ST 72
#define KS_ST 72
#define VS_ST 72
#define Q_TILE (128*QS_ST)   // halves
#define K_TILE (128*KS_ST)
#define V_TILE (128*VS_ST)
#define FLASH_SMEM ((Q_TILE + 2*K_TILE + 2*V_TILE) * 2)   // 92160 B

__global__ void __launch_bounds__(256, 1)
flash_kernel(const __half* __restrict__ Q, int ldq, long Qb,
             const __half* __restrict__ K, int ldk, long Kb,
             const __half* __restrict__ V, int ldv, long Vb,
             __half* __restrict__ O, int ldo, long Ob)
{
    extern __shared__ __half smh[];
    __half* Qs = smh;
    __half* Ks = smh + Q_TILE;
    __half* Vs = smh + Q_TILE + 2*K_TILE;

    const int tid  = threadIdx.x;
    const int wid  = tid >> 5, lane = tid & 31;
    const int g    = lane >> 2, t2 = (lane & 3) * 2;
    const int m0   = blockIdx.x * 128;
    const int wrow = wid * 16;

    {
        const int z = blockIdx.y;
        const int bb = z / Hn, hh = z - bb * Hn;
        Q += (long)bb * Qb + hh * 64;
        K += (long)bb * Kb + hh * 64;
        V += (long)bb * Vb + hh * 64;
        O += (long)bb * Ob + hh * 64;
    }

    auto loadQ = [&](){
#pragma unroll
        for (int idx = tid; idx < 1024; idx += 256) {
            const int r = idx >> 3, c = idx & 7;
            cp16(&Qs[r * QS_ST + c * 8], Q + (long)(m0 + r) * ldq + c * 8);
        }
    };
    auto loadK = [&](int kt, int s){
        __half* dst = Ks + s * K_TILE;
#pragma unroll
        for (int idx = tid; idx < 1024; idx += 256) {
            const int r = idx >> 3, c = idx & 7;
            cp16(&dst[r * KS_ST + c * 8], K + (long)(kt * 128 + r) * ldk + c * 8);
        }
    };
    auto loadV = [&](int kt, int s){
        __half* dst = Vs + s * V_TILE;
#pragma unroll
        for (int idx = tid; idx < 1024; idx += 256) {
            const int r = idx >> 3, c = idx & 7;
            cp16(&dst[r * VS_ST + c * 8], V + (long)(kt * 128 + r) * ldv + c * 8);
        }
    };

    float o[8][4];
#pragma unroll
    for (int i = 0; i < 8; i++)
#pragma unroll
        for (int j = 0; j < 4; j++) o[i][j] = 0.f;
    float m_a = -1e30f, m_b = -1e30f, l_a = 0.f, l_b = 0.f;

    loadQ(); loadK(0, 0); loadV(0, 0); CP_COMMIT();
    loadK(1, 1); loadV(1, 1); CP_COMMIT();

    for (int it = 0; it < 4; it++) {
        if (it >= 1) {
            __syncthreads();
            if (it + 1 < 4) { loadK(it + 1, (it + 1) & 1); loadV(it + 1, (it + 1) & 1); CP_COMMIT(); }
        }
        if (it + 1 < 4) CP_WAIT_1(); else CP_WAIT_0();
        __syncthreads();

        const __half* Kc = Ks + (it & 1) * K_TILE;
        const __half* Vc = Vs + (it & 1) * V_TILE;

        // ---- S = Q K^T ----
        float s[16][4];
#pragma unroll
        for (int nt = 0; nt < 16; nt++)
#pragma unroll
            for (int c = 0; c < 4; c++) s[nt][c] = 0.f;

#pragma unroll
        for (int kk = 0; kk < 64; kk += 16) {
            const int r = wrow + g;
            unsigned ra[4];
            ra[0] = *(const unsigned*)&Qs[r       * QS_ST + kk + t2];
            ra[1] = *(const unsigned*)&Qs[(r + 8) * QS_ST + kk + t2];
            ra[2] = *(const unsigned*)&Qs[r       * QS_ST + kk + t2 + 8];
            ra[3] = *(const unsigned*)&Qs[(r + 8) * QS_ST + kk + t2 + 8];
#pragma unroll
            for (int nt = 0; nt < 16; nt++) {
                const int kr = nt * 8 + g;
                unsigned rb[2];
                rb[0] = *(const unsigned*)&Kc[kr * KS_ST + kk + t2];
                rb[1] = *(const unsigned*)&Kc[kr * KS_ST + kk + t2 + 8];
                mma16816(s[nt], ra, rb);
            }
        }

        // ---- online softmax (scale 1/8 folded) ----
        float mx_a = -1e30f, mx_b = -1e30f;
#pragma unroll
        for (int nt = 0; nt < 16; nt++) {
#pragma unroll
            for (int c = 0; c < 4; c++) s[nt][c] *= 0.125f;
            mx_a = fmaxf(mx_a, fmaxf(s[nt][0], s[nt][1]));
            mx_b = fmaxf(mx_b, fmaxf(s[nt][2], s[nt][3]));
        }
        mx_a = fmaxf(mx_a, __shfl_xor_sync(0xffffffffu, mx_a, 1));
        mx_a = fmaxf(mx_a, __shfl_xor_sync(0xffffffffu, mx_a, 2));
        mx_b = fmaxf(mx_b, __shfl_xor_sync(0xffffffffu, mx_b, 1));
        mx_b = fmaxf(mx_b, __shfl_xor_sync(0xffffffffu, mx_b, 2));

        const float nm_a = fmaxf(m_a, mx_a);
        const float nm_b = fmaxf(m_b, mx_b);
        const float sc_a = __expf(m_a - nm_a);
        const float sc_b = __expf(m_b - nm_b);
        m_a = nm_a; m_b = nm_b;
        l_a *= sc_a; l_b *= sc_b;
#pragma unroll
        for (int nt = 0; nt < 8; nt++) {
            o[nt][0] *= sc_a; o[nt][1] *= sc_a;
            o[nt][2] *= sc_b; o[nt][3] *= sc_b;
        }
        float sum_a = 0.f, sum_b = 0.f;
#pragma unroll
        for (int nt = 0; nt < 16; nt++) {
            s[nt][0] = __expf(s[nt][0] - nm_a);
            s[nt][1] = __expf(s[nt][1] - nm_a);
            s[nt][2] = __expf(s[nt][2] - nm_b);
            s[nt][3] = __expf(s[nt][3] - nm_b);
            sum_a += s[nt][0] + s[nt][1];
            sum_b += s[nt][2] + s[nt][3];
        }
        l_a += sum_a; l_b += sum_b;

        // ---- O += P V ----
        const unsigned short* Vu = (const unsigned short*)Vc;
#pragma unroll
        for (int ks = 0; ks < 8; ks++) {
            unsigned ra[4];
            ra[0] = packf2(s[2*ks  ][0], s[2*ks  ][1]);
            ra[1] = packf2(s[2*ks  ][2], s[2*ks  ][3]);
            ra[2] = packf2(s[2*ks+1][0], s[2*ks+1][1]);
            ra[3] = packf2(s[2*ks+1][2], s[2*ks+1][3]);
            const int r0 = ks * 16 + t2;
#pragma unroll
            for (int nt = 0; nt < 8; nt++) {
                const int n = nt * 8 + g;
                unsigned b0 = (unsigned)Vu[(r0    ) * VS_ST + n]
                            | ((unsigned)Vu[(r0 + 1) * VS_ST + n] << 16);
                unsigned b1 = (unsigned)Vu[(r0 + 8) * VS_ST + n]
                            | ((unsigned)Vu[(r0 + 9) * VS_ST + n] << 16);
                unsigned rb[2] = {b0, b1};
                mma16816(o[nt], ra, rb);
            }
        }
    }

    l_a += __shfl_xor_sync(0xffffffffu, l_a, 1);
    l_a += __shfl_xor_sync(0xffffffffu, l_a, 2);
    l_b += __shfl_xor_sync(0xffffffffu, l_b, 1);
    l_b += __shfl_xor_sync(0xffffffffu, l_b, 2);
    const float inv_a = 1.f / l_a;
    const float inv_b = 1.f / l_b;

    const int row_a = m0 + wrow + g;
    const int row_b = row_a + 8;
#pragma unroll
    for (int nt = 0; nt < 8; nt++) {
        const int col = nt * 8 + t2;
        *(unsigned*)&O[(long)row_a * ldo + col] = packf2(o[nt][0] * inv_a, o[nt][1] * inv_a);
        *(unsigned*)&O[(long)row_b * ldo + col] = packf2(o[nt][2] * inv_b, o[nt][3] * inv_b);
    }
}

// ---------------- fp16 tensor-core GEMM, 4-stage cp.async, 1 sync/iter ----------------
// C[m,n] = sum_k A[m,k]*B[n,k]. ACT==1: exact GELU. OUTH: fp16 out else fp32 (+bias/resid).
#define GNS 4   // pipeline stages

template<int BM, int BN, int BK, int WM, int WN, int ACT, bool OUTH>
__global__ void __launch_bounds__(256, 2)
mma_gemm(const __half* __restrict__ A, int lda,
         const __half* __restrict__ B, int ldb,
         void* __restrict__ Cv, int ldc,
         int K,
         const float* __restrict__ bias,
         const float* __restrict__ resid, int ldr)
{
    constexpr int AST   = BK + 8;                      // 40 halves (80 B)
    constexpr int BST   = BK + 8;
    constexpr int A_TILE = BM * AST;                   // halves
    constexpr int B_TILE = BN * BST;
    constexpr int STAGE  = A_TILE + B_TILE;
    constexpr int NWN = BN / WN;
    constexpr int MT  = WM / 16;
    constexpr int NT  = WN / 8;

    extern __shared__ __half smh[];

    const int tid = threadIdx.x;
    const int wid = tid >> 5, lane = tid & 31;
    const int wm = wid / NWN, wn = wid % NWN;
    const int g  = lane >> 2, t2 = (lane & 3) * 2;

    const int m0 = blockIdx.y * BM, n0 = blockIdx.x * BN;

    float acc[MT][NT][4];
#pragma unroll
    for (int i = 0; i < MT; i++)
#pragma unroll
        for (int j = 0; j < NT; j++)
#pragma unroll
            for (int c = 0; c < 4; c++) acc[i][j][c] = 0.f;

    auto load_tiles = [&](int k0, int s){
        __half* Ad = smh + s * STAGE;
        __half* Bd = Ad + A_TILE;
        constexpr int ACH = BM * BK / 8;               // 16B chunks
#pragma unroll
        for (int idx = tid; idx < ACH; idx += 256) {
            const int r = idx / (BK / 8), c = idx % (BK / 8);
            cp16(&Ad[r * AST + c * 8], A + (long)(m0 + r) * lda + k0 + c * 8);
        }
        constexpr int BCH = BN * BK / 8;
#pragma unroll
        for (int idx = tid; idx < BCH; idx += 256) {
            const int r = idx / (BK / 8), c = idx % (BK / 8);
            cp16(&Bd[r * BST + c * 8], B + (long)(n0 + r) * ldb + k0 + c * 8);
        }
    };

    const int iters = K / BK;

    // prologue: stages 0..GNS-2, one commit group each
#pragma unroll
    for (int s = 0; s < GNS - 1; s++) {
        if (s < iters) load_tiles(s * BK, s);
        CP_COMMIT();
    }

    for (int it = 0; it < iters; it++) {
        // group `it` (data for this stage) is complete once pending <= GNS-2
        asm volatile("cp.async.wait_group %0;\n" :: "n"(GNS - 2) : "memory");
        __syncthreads();

        // issue loads GNS-1 chunks ahead (stage being overwritten was read at it-1)
        const int pf = it + GNS - 1;
        if (pf < iters) load_tiles(pf * BK, pf % GNS);
        CP_COMMIT();                                   // unconditional: keeps group count aligned

        const __half* Ac = smh + (it % GNS) * STAGE;
        const __half* Bc = Ac + A_TILE;

#pragma unroll
        for (int kk = 0; kk < BK; kk += 16) {
            unsigned rb[NT][2];
#pragma unroll
            for (int nt = 0; nt < NT; nt++) {
                const int r = wn * WN + nt * 8 + g;
                rb[nt][0] = *(const unsigned*)&Bc[r * BST + kk + t2];
                rb[nt][1] = *(const unsigned*)&Bc[r * BST + kk + t2 + 8];
            }
#pragma unroll
            for (int mt = 0; mt < MT; mt++) {
                const int r = wm * WM + mt * 16 + g;
                unsigned ra[4];
                ra[0] = *(const unsigned*)&Ac[r       * AST + kk + t2];
                ra[1] = *(const unsigned*)&Ac[(r + 8) * AST + kk + t2];
                ra[2] = *(const unsigned*)&Ac[r       * AST + kk + t2 + 8];
                ra[3] = *(const unsigned*)&Ac[(r + 8) * AST + kk + t2 + 8];
#pragma unroll
                for (int nt = 0; nt < NT; nt++)
                    mma16816(acc[mt][nt], ra, rb[nt]);
            }
        }
    }

    // ---------------- epilogue ----------------
#pragma unroll
    for (int mt = 0; mt < MT; mt++) {
#pragma unroll
        for (int nt = 0; nt < NT; nt++) {
            const int row0 = m0 + wm * WM + mt * 16 + g;
            const int col  = n0 + wn * WN + nt * 8 + t2;
#pragma unroll
            for (int half = 0; half < 2; half++) {
                const int row = row0 + half * 8;
                float v0 = acc[mt][nt][half * 2 + 0];
                float v1 = acc[mt][nt][half * 2 + 1];
                if (bias)  { v0 += bias[col]; v1 += bias[col + 1]; }
                if (resid) { v0 += resid[(long)row * ldr + col];
                             v1 += resid[(long)row * ldr + col + 1]; }
                if (ACT == 1) {
                    v0 = 0.5f * v0 * (1.0f + erff(v0 * 0.70710678118654752f));
                    v1 = 0.5f * v1 * (1.0f + erff(v1 * 0.70710678118654752f));
                }
                if (OUTH) {
                    *(unsigned*)((__half*)Cv + (long)row * ldc + col) = packf2(v0, v1);
                } else {
                    float2 w; w.x = v0; w.y = v1;
                    *(float2*)((float*)Cv + (long)row * ldc + col) = w;
                }
            }
        }
    }
}

// ---------------- launcher ----------------
extern "C" void kernel_launch(void* const* d_in, const int* in_sizes, int n_in,
                              void* d_out, int out_size)
{
    const float* q     = (const float*)d_in[0];
    const float* kv    = (const float*)d_in[1];
    const float* n1g   = (const float*)d_in[2];
    const float* n1b   = (const float*)d_in[3];
    const float* qkv_w = (const float*)d_in[4];
    const float* sa_pw = (const float*)d_in[5];
    const float* sa_pb = (const float*)d_in[6];
    const float* n2qg  = (const float*)d_in[7];
    const float* n2qb  = (const float*)d_in[8];
    const float* n2kg  = (const float*)d_in[9];
    const float* n2kb  = (const float*)d_in[10];
    const float* caq_w = (const float*)d_in[11];
    const float* cakv_w= (const float*)d_in[12];
    const float* cap_w = (const float*)d_in[13];
    const float* cap_b = (const float*)d_in[14];
    const float* n3g   = (const float*)d_in[15];
    const float* n3b   = (const float*)d_in[16];
    const float* fc1w  = (const float*)d_in[17];
    const float* fc1b  = (const float*)d_in[18];
    const float* fc2w  = (const float*)d_in[19];
    const float* fc2b  = (const float*)d_in[20];
    float* out = (float*)d_out;

    __half *x, *xkv, *qkvb, *attn, *qh, *kvp, *hid;
    __half *wqkv, *wsa, *wcaq, *wcakv, *wcap, *wfc1, *wfc2;
    float *q1, *q2;
    cudaGetSymbolAddress((void**)&x,    g_x);
    cudaGetSymbolAddress((void**)&xkv,  g_xkv);
    cudaGetSymbolAddress((void**)&qkvb, g_qkv);
    cudaGetSymbolAddress((void**)&attn, g_attn);
    cudaGetSymbolAddress((void**)&qh,   g_qh);
    cudaGetSymbolAddress((void**)&kvp,  g_kvp);
    cudaGetSymbolAddress((void**)&q1,   g_q1);
    cudaGetSymbolAddress((void**)&q2,   g_q2);
    cudaGetSymbolAddress((void**)&hid,  g_hid);
    cudaGetSymbolAddress((void**)&wqkv, g_wqkv);
    cudaGetSymbolAddress((void**)&wsa,  g_wsa);
    cudaGetSymbolAddress((void**)&wcaq, g_wcaq);
    cudaGetSymbolAddress((void**)&wcakv,g_wcakv);
    cudaGetSymbolAddress((void**)&wcap, g_wcap);
    cudaGetSymbolAddress((void**)&wfc1, g_wfc1);
    cudaGetSymbolAddress((void**)&wfc2, g_wfc2);

    const int SM_MAIN = (128*40 + 128*40) * GNS * 2;   // 81920 B (4 stages)
    cudaFuncSetAttribute(mma_gemm<128,128,32,64,32,0,true>,
                         cudaFuncAttributeMaxDynamicSharedMemorySize, SM_MAIN);
    cudaFuncSetAttribute(mma_gemm<128,128,32,64,32,0,false>,
                         cudaFuncAttributeMaxDynamicSharedMemorySize, SM_MAIN);
    cudaFuncSetAttribute(mma_gemm<128,128,32,64,32,1,true>,
                         cudaFuncAttributeMaxDynamicSharedMemorySize, SM_MAIN);
    cudaFuncSetAttribute(flash_kernel,
                         cudaFuncAttributeMaxDynamicSharedMemorySize, FLASH_SMEM);

    const dim3 blk(256);
    const long QKV_B = (long)LQn * 3 * Dm;
    const long TOK_B = (long)LQn * Dm;
    const long KVP_B = (long)LKVn * 2 * Dm;

    // ---- weight conversion (merged) ----
    {
        CvtArgs a;
        a.s[0]=qkv_w;  a.d[0]=wqkv;  a.n[0]=3*Dm*Dm;
        a.s[1]=sa_pw;  a.d[1]=wsa;   a.n[1]=Dm*Dm;
        a.s[2]=caq_w;  a.d[2]=wcaq;  a.n[2]=Dm*Dm;
        a.s[3]=cakv_w; a.d[3]=wcakv; a.n[3]=2*Dm*Dm;
        a.s[4]=cap_w;  a.d[4]=wcap;  a.n[4]=Dm*Dm;
        a.s[5]=fc1w;   a.d[5]=wfc1;  a.n[5]=HIDn*Dm;
        a.s[6]=fc2w;   a.d[6]=wfc2;  a.n[6]=Dm*HIDn;
        cvt_all<<<dim3((HIDn*Dm + 255)/256, 7), 256>>>(a);
    }

    // ===== self-attention =====
    ln_kernel<<<NTOK, 256>>>(q, n1g, n1b, x);

    mma_gemm<128,128,32,64,32,0,true><<<dim3(3*Dm/128, NTOK/128), blk, SM_MAIN>>>(
        x, Dm, wqkv, Dm, qkvb, 3*Dm, Dm, nullptr, nullptr, 0);

    flash_kernel<<<dim3(LQn/128, Bq*Hn), blk, FLASH_SMEM>>>(
        qkvb,        3*Dm, QKV_B,
        qkvb + Dm,   3*Dm, QKV_B,
        qkvb + 2*Dm, 3*Dm, QKV_B,
        attn, Dm, TOK_B);

    mma_gemm<128,128,32,64,32,0,false><<<dim3(Dm/128, NTOK/128), blk, SM_MAIN>>>(
        attn, Dm, wsa, Dm, q1, Dm, Dm, sa_pb, q, Dm);

    // ===== cross-attention =====
    ln_kernel<<<NTOK, 256>>>(q1, n2qg, n2qb, x);
    ln_kernel<<<NTOK, 256>>>(kv, n2kg, n2kb, xkv);

    mma_gemm<128,128,32,64,32,0,true><<<dim3(Dm/128, NTOK/128), blk, SM_MAIN>>>(
        x, Dm, wcaq, Dm, qh, Dm, Dm, nullptr, nullptr, 0);

    mma_gemm<128,128,32,64,32,0,true><<<dim3(2*Dm/128, NTOK/128), blk, SM_MAIN>>>(
        xkv, Dm, wcakv, Dm, kvp, 2*Dm, Dm, nullptr, nullptr, 0);

    flash_kernel<<<dim3(LQn/128, Bq*Hn), blk, FLASH_SMEM>>>(
        qh,        Dm,   TOK_B,
        kvp,       2*Dm, KVP_B,
        kvp + Dm,  2*Dm, KVP_B,
        attn, Dm, TOK_B);

    mma_gemm<128,128,32,64,32,0,false><<<dim3(Dm/128, NTOK/128), blk, SM_MAIN>>>(
        attn, Dm, wcap, Dm, q2, Dm, Dm, cap_b, q1, Dm);

    // ===== MLP =====
    ln_kernel<<<NTOK, 256>>>(q2, n3g, n3b, x);

    mma_gemm<128,128,32,64,32,1,true><<<dim3(HIDn/128, NTOK/128), blk, SM_MAIN>>>(
        x, Dm, wfc1, Dm, hid, HIDn, Dm, fc1b, nullptr, 0);

    mma_gemm<128,128,32,64,32,0,false><<<dim3(Dm/128, NTOK/128), blk, SM_MAIN>>>(
        hid, HIDn, wfc2, HIDn, out, Dm, HIDn, fc2b, q2, Dm);
}